// round 14
// baseline (speedup 1.0000x reference)
#include <cuda_runtime.h>
#include <cuda_bf16.h>
#include <math.h>
#include <stdint.h>

// Problem constants
#define S_LEN 2048
#define HID   4096
#define NH    32
#define NKV   8
#define HD    128
#define NQ    (NH * HD)    // 4096
#define NKVD  (NKV * HD)   // 1024
#define NQKV  (NQ + 2 * NKVD)  // 6144

// ---------------------------------------------------------------------------
// Scratch (static device arrays; no cudaMalloc allowed)
// ---------------------------------------------------------------------------
__device__ float g_hsr  [S_LEN * HID];     // hidden states, tf32-rounded
__device__ float g_wqkvT[NQKV * HID];      // [wq^T ; wk^T ; wv^T]  [6144][4096]
__device__ float g_qkv  [S_LEN * NQKV];    // QKV projection (Q region used)
__device__ float g_kh   [S_LEN * NKVD];    // K rope, head-major [NKV][S][HD]
__device__ float g_vt   [S_LEN * NKVD];    // V^T head-major [NKV][HD][S]
__device__ __nv_bfloat16 g_wTh[(size_t)HID * NQ];  // wo^T hi plane [HID][NQ]
__device__ __nv_bfloat16 g_wTl[(size_t)HID * NQ];  // wo^T lo plane
__device__ __nv_bfloat16 g_aoh[(size_t)S_LEN * NQ]; // attn out hi plane [S][NQ]
__device__ __nv_bfloat16 g_aol[(size_t)S_LEN * NQ]; // attn out lo plane

// ---------------------------------------------------------------------------
// Helpers
// ---------------------------------------------------------------------------
__device__ __forceinline__ uint32_t smem_u32(const void* p) {
    uint32_t a;
    asm("{ .reg .u64 t; cvta.to.shared.u64 t, %1; cvt.u32.u64 %0, t; }"
        : "=r"(a) : "l"(p));
    return a;
}
__device__ __forceinline__ float rna_tf32(float v) {
    uint32_t o;
    asm("cvt.rna.tf32.f32 %0, %1;" : "=r"(o) : "f"(v));
    return __uint_as_float(o);
}
__device__ __forceinline__ void mma_tf32(float* c, const uint32_t* a, const uint32_t* b) {
    asm("mma.sync.aligned.m16n8k8.row.col.f32.tf32.tf32.f32 "
        "{%0,%1,%2,%3}, {%4,%5,%6,%7}, {%8,%9}, {%0,%1,%2,%3};"
        : "+f"(c[0]), "+f"(c[1]), "+f"(c[2]), "+f"(c[3])
        : "r"(a[0]), "r"(a[1]), "r"(a[2]), "r"(a[3]), "r"(b[0]), "r"(b[1]));
}
__device__ __forceinline__ void mma_bf16(float* c, const uint32_t* a, const uint32_t* b) {
    asm("mma.sync.aligned.m16n8k16.row.col.f32.bf16.bf16.f32 "
        "{%0,%1,%2,%3}, {%4,%5,%6,%7}, {%8,%9}, {%0,%1,%2,%3};"
        : "+f"(c[0]), "+f"(c[1]), "+f"(c[2]), "+f"(c[3])
        : "r"(a[0]), "r"(a[1]), "r"(a[2]), "r"(a[3]), "r"(b[0]), "r"(b[1]));
}
__device__ __forceinline__ void ldsm_x4(uint32_t* r, uint32_t saddr) {
    asm volatile("ldmatrix.sync.aligned.m8n8.x4.shared.b16 {%0,%1,%2,%3}, [%4];"
        : "=r"(r[0]), "=r"(r[1]), "=r"(r[2]), "=r"(r[3]) : "r"(saddr));
}
__device__ __forceinline__ void cpasync16(uint32_t dst, const void* src) {
    asm volatile("cp.async.cg.shared.global [%0], [%1], 16;" :: "r"(dst), "l"(src));
}
#define CP_COMMIT()  asm volatile("cp.async.commit_group;" ::: "memory")
#define CP_WAIT0()   asm volatile("cp.async.wait_group 0;" ::: "memory")
#define CP_WAIT1()   asm volatile("cp.async.wait_group 1;" ::: "memory")

// ---------------------------------------------------------------------------
// Transpose tile (32n x 128k) + tf32 round: out[n][k] = rna(in[k][n]).
// ---------------------------------------------------------------------------
__device__ __forceinline__ void transpose_tile_rna(
    const float* __restrict__ in, float* __restrict__ out,
    int ldin, int ldout, int n0, int k0, float* tb)
{
    const int tx = threadIdx.x & 31;
    const int wy = threadIdx.x >> 5;
#pragma unroll
    for (int tt = 0; tt < 4; ++tt)
#pragma unroll
        for (int j = 0; j < 4; ++j)
            tb[(tt * 32 + wy + 8 * j) * 33 + tx] =
                in[(size_t)(k0 + tt * 32 + wy + 8 * j) * ldin + n0 + tx];
    __syncthreads();
#pragma unroll
    for (int tt = 0; tt < 4; ++tt)
#pragma unroll
        for (int j = 0; j < 4; ++j)
            out[(size_t)(n0 + wy + 8 * j) * ldout + k0 + tt * 32 + tx] =
                rna_tf32(tb[(tt * 32 + tx) * 33 + wy + 8 * j]);
}

// Transpose tile + bf16 hi/lo split: outh/outl[n][k] planes.
__device__ __forceinline__ void transpose_tile_bf16split(
    const float* __restrict__ in, __nv_bfloat16* __restrict__ outh,
    __nv_bfloat16* __restrict__ outl, int ldin, int ldout,
    int n0, int k0, float* tb)
{
    const int tx = threadIdx.x & 31;
    const int wy = threadIdx.x >> 5;
#pragma unroll
    for (int tt = 0; tt < 4; ++tt)
#pragma unroll
        for (int j = 0; j < 4; ++j)
            tb[(tt * 32 + wy + 8 * j) * 33 + tx] =
                in[(size_t)(k0 + tt * 32 + wy + 8 * j) * ldin + n0 + tx];
    __syncthreads();
#pragma unroll
    for (int tt = 0; tt < 4; ++tt)
#pragma unroll
        for (int j = 0; j < 4; ++j) {
            const float v = tb[(tt * 32 + tx) * 33 + wy + 8 * j];
            const __nv_bfloat16 hi = __float2bfloat16(v);
            const __nv_bfloat16 lo = __float2bfloat16(v - __bfloat162float(hi));
            const size_t idx = (size_t)(n0 + wy + 8 * j) * ldout + k0 + tt * 32 + tx;
            outh[idx] = hi;
            outl[idx] = lo;
        }
}

// ---------------------------------------------------------------------------
// tf32 mma GEMM body (unchanged; used for QKV). 128x128, 8 warps 64x32,
// BK=32, 3-stage cp.async. Epilogue modes: 0 plain, 1 rope-K, 2 V^T.
// ---------------------------------------------------------------------------
#define GBM 128
#define GBN 128
#define GBK 32
#define ASTR 36
#define BSTR 36
#define A_ST (128 * ASTR)
#define B_ST (128 * BSTR)
#define STAGE_FL (A_ST + B_ST)
#define GEMM_SMEM (3 * STAGE_FL * 4)   // 110592 B
#define EP_STR 132

__device__ __forceinline__ void gemm_load_stage(
    uint32_t a_dst, uint32_t b_dst, const float* ap, const float* bp, int K)
{
#pragma unroll
    for (int i = 0; i < 4; ++i)
        cpasync16(a_dst + i * 32 * ASTR * 4, ap + (size_t)i * 32 * K);
#pragma unroll
    for (int i = 0; i < 4; ++i)
        cpasync16(b_dst + i * 32 * BSTR * 4, bp + (size_t)i * 32 * K);
}

__device__ __forceinline__ void gemm_body(
    const float* __restrict__ A, const float* __restrict__ BT,
    float* __restrict__ C, int N, int K, int bm, int bn, float* sm,
    int mode, const float* __restrict__ cosp, const float* __restrict__ sinp,
    float* __restrict__ dst)
{
    const uint32_t sb = smem_u32(sm);
    const int tid  = threadIdx.x;
    const int lane = tid & 31;
    const int wid  = tid >> 5;
    const int wm   = wid >> 2;
    const int wn   = wid & 3;
    const int g    = lane >> 2;
    const int tig  = lane & 3;

    const int lrow = tid >> 3;
    const int lcol = (tid & 7) * 4;
    const float* Ap = A  + (size_t)(bm + lrow) * K + lcol;
    const float* Bp = BT + (size_t)(bn + lrow) * K + lcol;
    const uint32_t a_dst = sb + (uint32_t)(lrow * ASTR + lcol) * 4;
    const uint32_t b_dst = sb + (uint32_t)(A_ST + lrow * BSTR + lcol) * 4;

    const int a_r = wm * 64 + (lane & 7) + ((lane >> 3) & 1) * 8;
    const int a_c = (lane >> 4) * 4;
    const uint32_t a_frag = sb + (uint32_t)(a_r * ASTR + a_c) * 4;
    const int b_r = wn * 32 + ((lane >> 4) & 1) * 8 + (lane & 7);
    const int b_c = ((lane >> 3) & 1) * 4;
    const uint32_t b_frag = sb + (uint32_t)(A_ST + b_r * BSTR + b_c) * 4;

    float c[4][4][4];
#pragma unroll
    for (int mt = 0; mt < 4; ++mt)
#pragma unroll
        for (int nt = 0; nt < 4; ++nt)
#pragma unroll
            for (int i = 0; i < 4; ++i) c[mt][nt][i] = 0.0f;

    const int nkt = K / GBK;
    gemm_load_stage(a_dst, b_dst, Ap, Bp, K); CP_COMMIT();
    gemm_load_stage(a_dst + STAGE_FL * 4, b_dst + STAGE_FL * 4,
                    Ap + GBK, Bp + GBK, K); CP_COMMIT();

#pragma unroll 1
    for (int kt = 0; kt < nkt; ++kt) {
        if (kt + 1 < nkt) { CP_WAIT1(); } else { CP_WAIT0(); }
        __syncthreads();
        if (kt + 2 < nkt) {
            const uint32_t so = (uint32_t)((kt + 2) % 3) * STAGE_FL * 4;
            gemm_load_stage(a_dst + so, b_dst + so,
                            Ap + (kt + 2) * GBK, Bp + (kt + 2) * GBK, K);
        }
        CP_COMMIT();

        const uint32_t so = (uint32_t)(kt % 3) * STAGE_FL * 4;
#pragma unroll
        for (int ks = 0; ks < 4; ++ks) {
            uint32_t af[4][4];
#pragma unroll
            for (int mt = 0; mt < 4; ++mt)
                ldsm_x4(af[mt], a_frag + so + (uint32_t)(mt * 16 * ASTR + ks * 8) * 4);
            uint32_t bf[4][2];
#pragma unroll
            for (int p = 0; p < 2; ++p) {
                uint32_t t4[4];
                ldsm_x4(t4, b_frag + so + (uint32_t)(p * 16 * BSTR + ks * 8) * 4);
                bf[2 * p][0] = t4[0]; bf[2 * p][1] = t4[1];
                bf[2 * p + 1][0] = t4[2]; bf[2 * p + 1][1] = t4[3];
            }
#pragma unroll
            for (int mt = 0; mt < 4; ++mt)
#pragma unroll
                for (int nt = 0; nt < 4; ++nt)
                    mma_tf32(c[mt][nt], af[mt], bf[nt]);
        }
    }

    if (mode == 0) {
#pragma unroll
        for (int mt = 0; mt < 4; ++mt) {
            const int r0 = bm + wm * 64 + mt * 16 + g;
#pragma unroll
            for (int nt = 0; nt < 4; ++nt) {
                const int cc = bn + wn * 32 + nt * 8 + tig * 2;
                *(float2*)&C[(size_t)r0 * N + cc]       = make_float2(c[mt][nt][0], c[mt][nt][1]);
                *(float2*)&C[(size_t)(r0 + 8) * N + cc] = make_float2(c[mt][nt][2], c[mt][nt][3]);
            }
        }
        return;
    }

    // Fused K-rope / V^T epilogue: stage accumulators via smem.
    __syncthreads();
#pragma unroll
    for (int mt = 0; mt < 4; ++mt) {
        const int r0 = wm * 64 + mt * 16 + g;
#pragma unroll
        for (int nt = 0; nt < 4; ++nt) {
            const int cc = wn * 32 + nt * 8 + tig * 2;
            *(float2*)&sm[r0 * EP_STR + cc]       = make_float2(c[mt][nt][0], c[mt][nt][1]);
            *(float2*)&sm[(r0 + 8) * EP_STR + cc] = make_float2(c[mt][nt][2], c[mt][nt][3]);
        }
    }
    __syncthreads();

    if (mode == 1) {
        const int r    = tid >> 1;
        const int c0   = (tid & 1) * 64;
        const int srow = bm + r;
        const float sg = (c0 < 64) ? -1.0f : 1.0f;
#pragma unroll
        for (int i = 0; i < 16; ++i) {
            float4 x  = *(float4*)&sm[r * EP_STR + c0 + 4 * i];
            float4 p  = *(float4*)&sm[r * EP_STR + (c0 ^ 64) + 4 * i];
            float4 cv = *(const float4*)(cosp + (size_t)srow * HD + c0 + 4 * i);
            float4 sv = *(const float4*)(sinp + (size_t)srow * HD + c0 + 4 * i);
            float4 o;
            o.x = rna_tf32(x.x * cv.x + sg * p.x * sv.x);
            o.y = rna_tf32(x.y * cv.y + sg * p.y * sv.y);
            o.z = rna_tf32(x.z * cv.z + sg * p.z * sv.z);
            o.w = rna_tf32(x.w * cv.w + sg * p.w * sv.w);
            *(float4*)&dst[(size_t)srow * HD + c0 + 4 * i] = o;
        }
    } else {
        const int d  = tid >> 1;
        const int h2 = tid & 1;
#pragma unroll
        for (int i = 0; i < 16; ++i) {
            const int r = h2 * 64 + 4 * i;
            float4 o;
            o.x = rna_tf32(sm[(r + 0) * EP_STR + d]);
            o.y = rna_tf32(sm[(r + 1) * EP_STR + d]);
            o.z = rna_tf32(sm[(r + 2) * EP_STR + d]);
            o.w = rna_tf32(sm[(r + 3) * EP_STR + d]);
            *(float4*)&dst[(size_t)d * S_LEN + bm + r] = o;
        }
    }
}

// Fused QKV GEMM (+rope-K/V^T epilogues) + wo bf16-split-transpose tail.
#define QKV_GEMM_BLKS (48 * 16)      // 768
#define WO_T_BLKS     (128 * 32)     // 4096
__global__ __launch_bounds__(256, 2) void gemm_qkv_wo(
    const float* __restrict__ A, const float* __restrict__ BT,
    float* __restrict__ qkv, const float* __restrict__ wo,
    __nv_bfloat16* __restrict__ wTh, __nv_bfloat16* __restrict__ wTl,
    const float* __restrict__ cosp, const float* __restrict__ sinp,
    float* __restrict__ kh, float* __restrict__ vt)
{
    extern __shared__ float sm[];
    const int bid = blockIdx.x;
    if (bid < QKV_GEMM_BLKS) {
        const int tm = bid / 48, tn = bid % 48;
        const int bm = tm * GBM, bn = tn * GBN;
        if (tn < 32) {
            gemm_body(A, BT, qkv, NQKV, HID, bm, bn, sm, 0, 0, 0, 0);
        } else if (tn < 40) {
            gemm_body(A, BT, qkv, NQKV, HID, bm, bn, sm, 1, cosp, sinp,
                      kh + (size_t)(tn - 32) * S_LEN * HD);
        } else {
            gemm_body(A, BT, qkv, NQKV, HID, bm, bn, sm, 2, 0, 0,
                      vt + (size_t)(tn - 40) * HD * S_LEN);
        }
    } else {
        const int l = bid - QKV_GEMM_BLKS;
        transpose_tile_bf16split(wo, wTh, wTl, HID, NQ,
                                 (l % 128) * 32, (l / 128) * 128, sm);
    }
}

// ---------------------------------------------------------------------------
// bf16x3 GEMM (O-projection): C = Ah@Bh^T + Ah@Bl^T + Al@Bh^T, fp32 accum.
// A planes [M][K] bf16, B planes [N][K] bf16. 128x128 tile, BK=32 true-k,
// 2-stage cp.async, b16 ldsm (stride 40 bf16 = 80B, conflict-free).
// smem: 2 stages x 4 planes x 128x40 bf16 = 81920 B -> 2 CTAs/SM.
// ---------------------------------------------------------------------------
#define XSTR 40
#define XTILE (128 * XSTR)           // bf16 per plane tile
#define X_AH 0
#define X_AL (XTILE)
#define X_BH (2 * XTILE)
#define X_BL (3 * XTILE)
#define XSTAGE (4 * XTILE)           // bf16 per stage
#define XSMEM (2 * XSTAGE * 2)       // 81920 B

__device__ __forceinline__ void x_load_stage(
    uint32_t sbase, const __nv_bfloat16* Ah, const __nv_bfloat16* Al,
    const __nv_bfloat16* Bh, const __nv_bfloat16* Bl, int K,
    int bm, int bn, int k0, int tid)
{
    const int row = tid >> 1;
    const int cb  = (tid & 1) * 16;
    const uint32_t d = sbase + (uint32_t)(row * XSTR + cb) * 2;
#pragma unroll
    for (int i = 0; i < 2; ++i) {
        cpasync16(d + X_AH * 2 + i * 16, Ah + (size_t)(bm + row) * K + k0 + cb + 8 * i);
        cpasync16(d + X_AL * 2 + i * 16, Al + (size_t)(bm + row) * K + k0 + cb + 8 * i);
        cpasync16(d + X_BH * 2 + i * 16, Bh + (size_t)(bn + row) * K + k0 + cb + 8 * i);
        cpasync16(d + X_BL * 2 + i * 16, Bl + (size_t)(bn + row) * K + k0 + cb + 8 * i);
    }
}

__global__ __launch_bounds__(256, 2) void gemm_bf16x3(
    const __nv_bfloat16* __restrict__ Ah, const __nv_bfloat16* __restrict__ Al,
    const __nv_bfloat16* __restrict__ Bh, const __nv_bfloat16* __restrict__ Bl,
    float* __restrict__ C, int M, int N, int K)
{
    extern __shared__ float smx[];
    const uint32_t sb = smem_u32(smx);
    const int tid  = threadIdx.x;
    const int lane = tid & 31;
    const int wid  = tid >> 5;
    const int wm   = wid >> 2;
    const int wn   = wid & 3;
    const int g    = lane >> 2;
    const int tig  = lane & 3;
    const int bm   = blockIdx.y * 128;
    const int bn   = blockIdx.x * 128;

    // ldmatrix lane bases (bf16, bytes)
    const int rsel = (lane & 7) + ((lane >> 3) & 1) * 8;
    const int c8   = (lane >> 4) * 8;
    const uint32_t a_off = (uint32_t)((wm * 64 + rsel) * XSTR + c8) * 2;
    const uint32_t b_off = (uint32_t)((wn * 32 + rsel) * XSTR + c8) * 2;

    float c[4][4][4];
#pragma unroll
    for (int mt = 0; mt < 4; ++mt)
#pragma unroll
        for (int nt = 0; nt < 4; ++nt)
#pragma unroll
            for (int i = 0; i < 4; ++i) c[mt][nt][i] = 0.0f;

    const int nkt = K / 32;
    x_load_stage(sb, Ah, Al, Bh, Bl, K, bm, bn, 0, tid);  CP_COMMIT();
    x_load_stage(sb + XSTAGE * 2, Ah, Al, Bh, Bl, K, bm, bn, 32, tid); CP_COMMIT();

#pragma unroll 1
    for (int kt = 0; kt < nkt; ++kt) {
        if (kt + 1 < nkt) { CP_WAIT1(); } else { CP_WAIT0(); }
        __syncthreads();

        const uint32_t so = (uint32_t)(kt & 1) * XSTAGE * 2;
#pragma unroll
        for (int ks = 0; ks < 2; ++ks) {
            const uint32_t kso = (uint32_t)(ks * 16) * 2;
            uint32_t ah[4][4];
#pragma unroll
            for (int mt = 0; mt < 4; ++mt)
                ldsm_x4(ah[mt], sb + so + X_AH * 2 + a_off + (uint32_t)(mt * 16 * XSTR) * 2 + kso);
            uint32_t bh[4][2];
#pragma unroll
            for (int p = 0; p < 2; ++p) {
                uint32_t t4[4];
                ldsm_x4(t4, sb + so + X_BH * 2 + b_off + (uint32_t)(p * 16 * XSTR) * 2 + kso);
                bh[2 * p][0] = t4[0]; bh[2 * p][1] = t4[2];
                bh[2 * p + 1][0] = t4[1]; bh[2 * p + 1][1] = t4[3];
            }
#pragma unroll
            for (int mt = 0; mt < 4; ++mt)
#pragma unroll
                for (int nt = 0; nt < 4; ++nt)
                    mma_bf16(c[mt][nt], ah[mt], bh[nt]);     // hh

            uint32_t bl[4][2];
#pragma unroll
            for (int p = 0; p < 2; ++p) {
                uint32_t t4[4];
                ldsm_x4(t4, sb + so + X_BL * 2 + b_off + (uint32_t)(p * 16 * XSTR) * 2 + kso);
                bl[2 * p][0] = t4[0]; bl[2 * p][1] = t4[2];
                bl[2 * p + 1][0] = t4[1]; bl[2 * p + 1][1] = t4[3];
            }
#pragma unroll
            for (int mt = 0; mt < 4; ++mt)
#pragma unroll
                for (int nt = 0; nt < 4; ++nt)
                    mma_bf16(c[mt][nt], ah[mt], bl[nt]);     // hl

            uint32_t al[4][4];
#pragma unroll
            for (int mt = 0; mt < 4; ++mt)
                ldsm_x4(al[mt], sb + so + X_AL * 2 + a_off + (uint32_t)(mt * 16 * XSTR) * 2 + kso);
#pragma unroll
            for (int mt = 0; mt < 4; ++mt)
#pragma unroll
                for (int nt = 0; nt < 4; ++nt)
                    mma_bf16(c[mt][nt], al[mt], bh[nt]);     // lh
        }

        __syncthreads();
        if (kt + 2 < nkt)
            x_load_stage(sb + (uint32_t)(kt & 1) * XSTAGE * 2,
                         Ah, Al, Bh, Bl, K, bm, bn, (kt + 2) * 32, tid);
        CP_COMMIT();
    }

#pragma unroll
    for (int mt = 0; mt < 4; ++mt) {
        const int r0 = bm + wm * 64 + mt * 16 + g;
#pragma unroll
        for (int nt = 0; nt < 4; ++nt) {
            const int cc = bn + wn * 32 + nt * 8 + tig * 2;
            *(float2*)&C[(size_t)r0 * N + cc]       = make_float2(c[mt][nt][0], c[mt][nt][1]);
            *(float2*)&C[(size_t)(r0 + 8) * N + cc] = make_float2(c[mt][nt][2], c[mt][nt][3]);
        }
    }
}

// ---------------------------------------------------------------------------
// Fused pre-pass: round(hidden) + wq/wk/wv transposes, one launch.
// ---------------------------------------------------------------------------
#define PREP_ROUND_BLKS (S_LEN * HID / 4 / 256)   // 8192
#define PREP_WQ_BLKS    (128 * 32)                // 4096
#define PREP_WK_BLKS    (32 * 32)                 // 1024
#define PREP_WV_BLKS    (32 * 32)                 // 1024
#define PREP_BLKS (PREP_ROUND_BLKS + PREP_WQ_BLKS + PREP_WK_BLKS + PREP_WV_BLKS)

__global__ __launch_bounds__(256) void prep_fused(
    const float* __restrict__ hs, const float* __restrict__ wq,
    const float* __restrict__ wk, const float* __restrict__ wv,
    float* __restrict__ hsr, float* __restrict__ wqkvT)
{
    __shared__ float tb[4 * 32 * 33];
    int bid = blockIdx.x;
    if (bid < PREP_ROUND_BLKS) {
        const int i = bid * 256 + threadIdx.x;
        float4 v = ((const float4*)hs)[i];
        v.x = rna_tf32(v.x); v.y = rna_tf32(v.y);
        v.z = rna_tf32(v.z); v.w = rna_tf32(v.w);
        ((float4*)hsr)[i] = v;
        return;
    }
    bid -= PREP_ROUND_BLKS;
    if (bid < PREP_WQ_BLKS) {
        transpose_tile_rna(wq, wqkvT, NQ, HID, (bid % 128) * 32, (bid / 128) * 128, tb);
        return;
    }
    bid -= PREP_WQ_BLKS;
    if (bid < PREP_WK_BLKS) {
        transpose_tile_rna(wk, wqkvT + (size_t)NQ * HID, NKVD, HID,
                           (bid % 32) * 32, (bid / 32) * 128, tb);
        return;
    }
    bid -= PREP_WK_BLKS;
    transpose_tile_rna(wv, wqkvT + (size_t)(NQ + NKVD) * HID, NKVD, HID,
                       (bid % 32) * 32, (bid / 32) * 128, tb);
}

// ---------------------------------------------------------------------------
// Flash attention, 2 CTAs/SM. BM=64, BN=64, 4 warps. Shuffle-P, fused Q-rope,
// 3 barriers/jt. Epilogue writes bf16 hi/lo planes (feeds bf16x3 O-proj).
// ---------------------------------------------------------------------------
#define FB_QSTR 132
#define FB_KSTR 132
#define FB_VSTR 68
#define FB_QS 0
#define FB_KS (64 * FB_QSTR)
#define FB_VT (FB_KS + 64 * FB_KSTR)
#define FB_SMEM ((FB_VT + 128 * FB_VSTR) * 4)   // 102400 B

__global__ __launch_bounds__(128, 2) void flash_mma(
    const float* __restrict__ QKV, const float* __restrict__ cosp,
    const float* __restrict__ sinp, const float* __restrict__ Kh,
    const float* __restrict__ VT, __nv_bfloat16* __restrict__ Oh,
    __nv_bfloat16* __restrict__ Ol)
{
    extern __shared__ float sm[];
    const uint32_t sb = smem_u32(sm);

    const int tid  = threadIdx.x;
    const int lane = tid & 31;
    const int wid  = tid >> 5;
    const int g    = lane >> 2;
    const int tig  = lane & 3;
    const int qb   = gridDim.x - 1 - blockIdx.x;
    const int h    = blockIdx.y;
    const int kvh  = h >> 2;

    const float* Kbase  = Kh + (size_t)kvh * S_LEN * HD;
    const float* VTbase = VT + (size_t)kvh * HD * S_LEN;

    // Stage Q tile [64][128] with inline RoPE
#pragma unroll
    for (int j = 0; j < 16; ++j) {
        const int idx = tid + j * 128;
        const int r = idx >> 5, cb = (idx & 31) * 4;
        const int srow = qb * 64 + r;
        const float* qrow = QKV + (size_t)srow * NQKV + h * HD;
        float4 x  = *(const float4*)(qrow + cb);
        float4 p  = *(const float4*)(qrow + (cb ^ 64));
        float4 c4 = *(const float4*)(cosp + srow * HD + cb);
        float4 s4 = *(const float4*)(sinp + srow * HD + cb);
        const float sg = (cb < 64) ? -1.0f : 1.0f;
        sm[FB_QS + r * FB_QSTR + cb + 0] = rna_tf32(x.x * c4.x + sg * p.x * s4.x);
        sm[FB_QS + r * FB_QSTR + cb + 1] = rna_tf32(x.y * c4.y + sg * p.y * s4.y);
        sm[FB_QS + r * FB_QSTR + cb + 2] = rna_tf32(x.z * c4.z + sg * p.z * s4.z);
        sm[FB_QS + r * FB_QSTR + cb + 3] = rna_tf32(x.w * c4.w + sg * p.w * s4.w);
    }

    const int rsel  = (lane & 7) + ((lane >> 3) & 1) * 8;
    const int csel  = (lane >> 4) * 4;
    const int brsel = ((lane >> 4) & 1) * 8 + (lane & 7);
    const int bcsel = ((lane >> 3) & 1) * 4;
    const uint32_t q_frag = sb + (uint32_t)(FB_QS + (wid * 16 + rsel) * FB_QSTR + csel) * 4;
    const uint32_t k_frag = sb + (uint32_t)(FB_KS + brsel * FB_KSTR + bcsel) * 4;
    const uint32_t v_frag = sb + (uint32_t)(FB_VT + brsel * FB_VSTR + bcsel) * 4;

    float s[8][4], o[16][4], m_i[2], l_i[2];
    m_i[0] = m_i[1] = -1e30f;
    l_i[0] = l_i[1] = 0.0f;
#pragma unroll
    for (int nt = 0; nt < 16; ++nt)
#pragma unroll
        for (int i = 0; i < 4; ++i) o[nt][i] = 0.0f;

    const float sc = 0.08838834764831845f;
    const int qrow0 = qb * 64 + wid * 16 + g;
    const int jtmax = qb;

#pragma unroll
    for (int j = 0; j < 16; ++j) {
        const int idx = tid + j * 128;
        const int r = idx >> 5, c = (idx & 31) * 4;
        cpasync16(sb + (uint32_t)(FB_KS + r * FB_KSTR + c) * 4,
                  Kbase + (size_t)r * HD + c);
    }
    CP_COMMIT();
#pragma unroll
    for (int j = 0; j < 16; ++j) {
        const int idx = tid + j * 128;
        const int d = idx >> 4, c = (idx & 15) * 4;
        cpasync16(sb + (uint32_t)(FB_VT + d * FB_VSTR + c) * 4,
                  VTbase + (size_t)d * S_LEN + c);
    }
    CP_COMMIT();

    for (int jt = 0; jt <= jtmax; ++jt) {
        CP_WAIT1();
        __syncthreads();

#pragma unroll
        for (int nt = 0; nt < 8; ++nt)
#pragma unroll
            for (int i = 0; i < 4; ++i) s[nt][i] = 0.0f;

#pragma unroll
        for (int ks = 0; ks < 16; ++ks) {
            uint32_t a[4];
            ldsm_x4(a, q_frag + ks * 32);
#pragma unroll
            for (int p = 0; p < 4; ++p) {
                uint32_t t4[4];
                ldsm_x4(t4, k_frag + (uint32_t)(p * 16 * FB_KSTR) * 4 + ks * 32);
                mma_tf32(s[2 * p],     a, t4);
                mma_tf32(s[2 * p + 1], a, t4 + 2);
            }
        }

        const int colb = jt * 64 + tig * 2;
#pragma unroll
        for (int nt = 0; nt < 8; ++nt) {
            const int c0 = colb + nt * 8, c1 = c0 + 1;
            s[nt][0] = (c0 > qrow0)     ? -1e30f : s[nt][0] * sc;
            s[nt][1] = (c1 > qrow0)     ? -1e30f : s[nt][1] * sc;
            s[nt][2] = (c0 > qrow0 + 8) ? -1e30f : s[nt][2] * sc;
            s[nt][3] = (c1 > qrow0 + 8) ? -1e30f : s[nt][3] * sc;
        }

        float mx0 = -1e30f, mx1 = -1e30f;
#pragma unroll
        for (int nt = 0; nt < 8; ++nt) {
            mx0 = fmaxf(mx0, fmaxf(s[nt][0], s[nt][1]));
            mx1 = fmaxf(mx1, fmaxf(s[nt][2], s[nt][3]));
        }
        mx0 = fmaxf(mx0, __shfl_xor_sync(0xffffffffu, mx0, 1));
        mx0 = fmaxf(mx0, __shfl_xor_sync(0xffffffffu, mx0, 2));
        mx1 = fmaxf(mx1, __shfl_xor_sync(0xffffffffu, mx1, 1));
        mx1 = fmaxf(mx1, __shfl_xor_sync(0xffffffffu, mx1, 2));

        const float mn0 = fmaxf(m_i[0], mx0);
        const float mn1 = fmaxf(m_i[1], mx1);
        const float al0 = __expf(m_i[0] - mn0);
        const float al1 = __expf(m_i[1] - mn1);
        m_i[0] = mn0; m_i[1] = mn1;

        float rs0 = 0.0f, rs1 = 0.0f;
#pragma unroll
        for (int nt = 0; nt < 8; ++nt) {
            s[nt][0] = __expf(s[nt][0] - mn0);
            s[nt][1] = __expf(s[nt][1] - mn0);
            s[nt][2] = __expf(s[nt][2] - mn1);
            s[nt][3] = __expf(s[nt][3] - mn1);
            rs0 += s[nt][0] + s[nt][1];
            rs1 += s[nt][2] + s[nt][3];
        }
        rs0 += __shfl_xor_sync(0xffffffffu, rs0, 1);
        rs0 += __shfl_xor_sync(0xffffffffu, rs0, 2);
        rs1 += __shfl_xor_sync(0xffffffffu, rs1, 1);
        rs1 += __shfl_xor_sync(0xffffffffu, rs1, 2);
        l_i[0] = l_i[0] * al0 + rs0;
        l_i[1] = l_i[1] * al1 + rs1;
#pragma unroll
        for (int nt = 0; nt < 16; ++nt) {
            o[nt][0] *= al0; o[nt][1] *= al0;
            o[nt][2] *= al1; o[nt][3] *= al1;
        }

        CP_WAIT0();
        __syncthreads();
        if (jt < jtmax) {
#pragma unroll
            for (int j = 0; j < 16; ++j) {
                const int idx = tid + j * 128;
                const int r = idx >> 5, c = (idx & 31) * 4;
                cpasync16(sb + (uint32_t)(FB_KS + r * FB_KSTR + c) * 4,
                          Kbase + (size_t)((jt + 1) * 64 + r) * HD + c);
            }
        }
        CP_COMMIT();

        const int qbase = lane & ~3;
        const int srcA  = qbase | (tig >> 1);
        const int srcB  = srcA + 2;
        const bool odd  = (tig & 1);
#pragma unroll
        for (int ks = 0; ks < 8; ++ks) {
            const float p0 = s[ks][0], p1 = s[ks][1];
            const float p2 = s[ks][2], p3 = s[ks][3];
            const float a0A = __shfl_sync(0xffffffffu, p0, srcA);
            const float a1A = __shfl_sync(0xffffffffu, p1, srcA);
            const float a2A = __shfl_sync(0xffffffffu, p2, srcA);
            const float a3A = __shfl_sync(0xffffffffu, p3, srcA);
            const float a0B = __shfl_sync(0xffffffffu, p0, srcB);
            const float a1B = __shfl_sync(0xffffffffu, p1, srcB);
            const float a2B = __shfl_sync(0xffffffffu, p2, srcB);
            const float a3B = __shfl_sync(0xffffffffu, p3, srcB);
            uint32_t a[4];
            a[0] = __float_as_uint(rna_tf32(odd ? a1A : a0A));
            a[1] = __float_as_uint(rna_tf32(odd ? a3A : a2A));
            a[2] = __float_as_uint(rna_tf32(odd ? a1B : a0B));
            a[3] = __float_as_uint(rna_tf32(odd ? a3B : a2B));
#pragma unroll
            for (int p = 0; p < 8; ++p) {
                uint32_t t4[4];
                ldsm_x4(t4, v_frag + (uint32_t)(p * 16 * FB_VSTR) * 4 + ks * 32);
                mma_tf32(o[2 * p],     a, t4);
                mma_tf32(o[2 * p + 1], a, t4 + 2);
            }
        }

        __syncthreads();
        if (jt < jtmax) {
#pragma unroll
            for (int j = 0; j < 16; ++j) {
                const int idx = tid + j * 128;
                const int d = idx >> 4, c = (idx & 15) * 4;
                cpasync16(sb + (uint32_t)(FB_VT + d * FB_VSTR + c) * 4,
                          VTbase + (size_t)d * S_LEN + (jt + 1) * 64 + c);
            }
        }
        CP_COMMIT();
    }

    // Epilogue: normalize, split into bf16 hi/lo planes.
    const float inv0 = 1.0f / l_i[0];
    const float inv1 = 1.0f / l_i[1];
    const size_t obase = (size_t)qrow0 * NQ + h * HD;
#pragma unroll
    for (int nt = 0; nt < 16; ++nt) {
        const int cc = nt * 8 + tig * 2;
#pragma unroll
        for (int half = 0; half < 2; ++half) {
            const float inv = half ? inv1 : inv0;
            const size_t idx = obase + (size_t)(half * 8) * NQ + cc;
            const float v0 = o[nt][2 * half + 0] * inv;
            const float v1 = o[nt][2 * half + 1] * inv;
            const __nv_bfloat16 h0 = __float2bfloat16(v0);
            const __nv_bfloat16 h1 = __float2bfloat16(v1);
            const __nv_bfloat16 l0 = __float2bfloat16(v0 - __bfloat162float(h0));
            const __nv_bfloat16 l1 = __float2bfloat16(v1 - __bfloat162float(h1));
            *(__nv_bfloat162*)&Oh[idx] = __nv_bfloat162(h0, h1);
            *(__nv_bfloat162*)&Ol[idx] = __nv_bfloat162(l0, l1);
        }
    }
}

// ---------------------------------------------------------------------------
// Launch. Inputs: 0 hidden_states, 1 attention_mask (unused), 2 wq, 3 wk,
// 4 wv, 5 wo, 6 cos, 7 sin.
// ---------------------------------------------------------------------------
extern "C" void kernel_launch(void* const* d_in, const int* in_sizes, int n_in,
                              void* d_out, int out_size)
{
    (void)in_sizes; (void)n_in; (void)out_size;
    const float* hs = (const float*)d_in[0];
    const float* wq = (const float*)d_in[2];
    const float* wk = (const float*)d_in[3];
    const float* wv = (const float*)d_in[4];
    const float* wo = (const float*)d_in[5];
    const float* cs = (const float*)d_in[6];
    const float* sn = (const float*)d_in[7];
    float* out = (float*)d_out;

    float *hsr, *wqkvT, *qkv, *kh, *vt;
    __nv_bfloat16 *wTh, *wTl, *aoh, *aol;
    cudaGetSymbolAddress((void**)&hsr,   g_hsr);
    cudaGetSymbolAddress((void**)&wqkvT, g_wqkvT);
    cudaGetSymbolAddress((void**)&qkv,   g_qkv);
    cudaGetSymbolAddress((void**)&kh,    g_kh);
    cudaGetSymbolAddress((void**)&vt,    g_vt);
    cudaGetSymbolAddress((void**)&wTh,   g_wTh);
    cudaGetSymbolAddress((void**)&wTl,   g_wTl);
    cudaGetSymbolAddress((void**)&aoh,   g_aoh);
    cudaGetSymbolAddress((void**)&aol,   g_aol);

    cudaFuncSetAttribute(gemm_qkv_wo, cudaFuncAttributeMaxDynamicSharedMemorySize, GEMM_SMEM);
    cudaFuncSetAttribute(flash_mma,   cudaFuncAttributeMaxDynamicSharedMemorySize, FB_SMEM);
    cudaFuncSetAttribute(gemm_bf16x3, cudaFuncAttributeMaxDynamicSharedMemorySize, XSMEM);

    // #1: fused pre-pass (round + wq/wk/wv transposes)
    prep_fused<<<PREP_BLKS, 256>>>(hs, wq, wk, wv, hsr, wqkvT);

    // #2: QKV GEMM (+rope-K/V^T epilogues) + wo bf16-split-transpose tail
    gemm_qkv_wo<<<QKV_GEMM_BLKS + WO_T_BLKS, 256, GEMM_SMEM>>>(
        hsr, wqkvT, qkv, wo, wTh, wTl, cs, sn, kh, vt);

    // #3: flash attention (writes bf16 hi/lo output planes)
    flash_mma<<<dim3(S_LEN / 64, NH), 128, FB_SMEM>>>(qkv, cs, sn, kh, vt, aoh, aol);

    // #4: output projection on bf16x3
    gemm_bf16x3<<<dim3(HID / 128, S_LEN / 128), 256, XSMEM>>>(
        aoh, aol, wTh, wTl, out, S_LEN, HID, NQ);
}

// round 15
// speedup vs baseline: 1.2009x; 1.2009x over previous
#include <cuda_runtime.h>
#include <cuda_bf16.h>
#include <math.h>
#include <stdint.h>

// Problem constants
#define S_LEN 2048
#define HID   4096
#define NH    32
#define NKV   8
#define HD    128
#define NQ    (NH * HD)    // 4096
#define NKVD  (NKV * HD)   // 1024
#define NQKV  (NQ + 2 * NKVD)  // 6144

// ---------------------------------------------------------------------------
// Scratch (static device arrays; no cudaMalloc allowed)
// ---------------------------------------------------------------------------
__device__ float g_wqkvT[NQKV * HID];      // [wq^T ; wk^T ; wv^T]  [6144][4096]
__device__ float g_woT  [HID * NQ];        // wo^T  [4096][4096]
__device__ float g_qkv  [S_LEN * NQKV];    // QKV projection (Q region used)
__device__ float g_kh   [S_LEN * NKVD];    // K rope, head-major [NKV][S][HD]
__device__ float g_vt   [S_LEN * NKVD];    // V^T head-major [NKV][HD][S]
__device__ float g_ao   [S_LEN * NQ];      // attention out [S][4096]

// ---------------------------------------------------------------------------
// Helpers
// ---------------------------------------------------------------------------
__device__ __forceinline__ uint32_t smem_u32(const void* p) {
    uint32_t a;
    asm("{ .reg .u64 t; cvta.to.shared.u64 t, %1; cvt.u32.u64 %0, t; }"
        : "=r"(a) : "l"(p));
    return a;
}
__device__ __forceinline__ float rna_tf32(float v) {
    uint32_t o;
    asm("cvt.rna.tf32.f32 %0, %1;" : "=r"(o) : "f"(v));
    return __uint_as_float(o);
}
__device__ __forceinline__ uint32_t rna_tf32_u(uint32_t v) {
    uint32_t o;
    asm("cvt.rna.tf32.f32 %0, %1;" : "=r"(o) : "r"(v));
    return o;
}
__device__ __forceinline__ void mma_tf32(float* c, const uint32_t* a, const uint32_t* b) {
    asm("mma.sync.aligned.m16n8k8.row.col.f32.tf32.tf32.f32 "
        "{%0,%1,%2,%3}, {%4,%5,%6,%7}, {%8,%9}, {%0,%1,%2,%3};"
        : "+f"(c[0]), "+f"(c[1]), "+f"(c[2]), "+f"(c[3])
        : "r"(a[0]), "r"(a[1]), "r"(a[2]), "r"(a[3]), "r"(b[0]), "r"(b[1]));
}
__device__ __forceinline__ void ldsm_x4(uint32_t* r, uint32_t saddr) {
    asm volatile("ldmatrix.sync.aligned.m8n8.x4.shared.b16 {%0,%1,%2,%3}, [%4];"
        : "=r"(r[0]), "=r"(r[1]), "=r"(r[2]), "=r"(r[3]) : "r"(saddr));
}
__device__ __forceinline__ void cpasync16(uint32_t dst, const void* src) {
    asm volatile("cp.async.cg.shared.global [%0], [%1], 16;" :: "r"(dst), "l"(src));
}
#define CP_COMMIT()  asm volatile("cp.async.commit_group;" ::: "memory")
#define CP_WAIT0()   asm volatile("cp.async.wait_group 0;" ::: "memory")
#define CP_WAIT1()   asm volatile("cp.async.wait_group 1;" ::: "memory")

// ---------------------------------------------------------------------------
// Shared transpose tile (32n x 128k) + tf32 round: out[n][k] = rna(in[k][n]).
// ---------------------------------------------------------------------------
__device__ __forceinline__ void transpose_tile_rna(
    const float* __restrict__ in, float* __restrict__ out,
    int ldin, int ldout, int n0, int k0, float* tb)
{
    const int tx = threadIdx.x & 31;
    const int wy = threadIdx.x >> 5;  // 0..7
#pragma unroll
    for (int tt = 0; tt < 4; ++tt)
#pragma unroll
        for (int j = 0; j < 4; ++j)
            tb[(tt * 32 + wy + 8 * j) * 33 + tx] =
                in[(size_t)(k0 + tt * 32 + wy + 8 * j) * ldin + n0 + tx];
    __syncthreads();
#pragma unroll
    for (int tt = 0; tt < 4; ++tt)
#pragma unroll
        for (int j = 0; j < 4; ++j)
            out[(size_t)(n0 + wy + 8 * j) * ldout + k0 + tt * 32 + tx] =
                rna_tf32(tb[(tt * 32 + tx) * 33 + wy + 8 * j]);
}

// ---------------------------------------------------------------------------
// tf32 mma GEMM body: 128x128 block tile, 8 warps of 64x32 warp tiles,
// BK=32, 3-stage cp.async, ldmatrix. 2 CTAs/SM. A-fragments are tf32-rounded
// IN REGISTERS after ldsm (lets A be raw fp32 in gmem; rna is idempotent on
// pre-rounded inputs). B must be pre-rounded (weights are).
// Epilogue modes: 0 plain, 1 rope-K, 2 V^T.
// ---------------------------------------------------------------------------
#define GBM 128
#define GBN 128
#define GBK 32
#define ASTR 36
#define BSTR 36
#define A_ST (128 * ASTR)
#define B_ST (128 * BSTR)
#define STAGE_FL (A_ST + B_ST)
#define GEMM_SMEM (3 * STAGE_FL * 4)   // 110592 B
#define EP_STR 132

__device__ __forceinline__ void gemm_load_stage(
    uint32_t a_dst, uint32_t b_dst, const float* ap, const float* bp, int K)
{
#pragma unroll
    for (int i = 0; i < 4; ++i)
        cpasync16(a_dst + i * 32 * ASTR * 4, ap + (size_t)i * 32 * K);
#pragma unroll
    for (int i = 0; i < 4; ++i)
        cpasync16(b_dst + i * 32 * BSTR * 4, bp + (size_t)i * 32 * K);
}

__device__ __forceinline__ void gemm_body(
    const float* __restrict__ A, const float* __restrict__ BT,
    float* __restrict__ C, int N, int K, int bm, int bn, float* sm,
    int mode, const float* __restrict__ cosp, const float* __restrict__ sinp,
    float* __restrict__ dst)
{
    const uint32_t sb = smem_u32(sm);
    const int tid  = threadIdx.x;
    const int lane = tid & 31;
    const int wid  = tid >> 5;
    const int wm   = wid >> 2;
    const int wn   = wid & 3;
    const int g    = lane >> 2;
    const int tig  = lane & 3;

    const int lrow = tid >> 3;
    const int lcol = (tid & 7) * 4;
    const float* Ap = A  + (size_t)(bm + lrow) * K + lcol;
    const float* Bp = BT + (size_t)(bn + lrow) * K + lcol;
    const uint32_t a_dst = sb + (uint32_t)(lrow * ASTR + lcol) * 4;
    const uint32_t b_dst = sb + (uint32_t)(A_ST + lrow * BSTR + lcol) * 4;

    const int a_r = wm * 64 + (lane & 7) + ((lane >> 3) & 1) * 8;
    const int a_c = (lane >> 4) * 4;
    const uint32_t a_frag = sb + (uint32_t)(a_r * ASTR + a_c) * 4;
    const int b_r = wn * 32 + ((lane >> 4) & 1) * 8 + (lane & 7);
    const int b_c = ((lane >> 3) & 1) * 4;
    const uint32_t b_frag = sb + (uint32_t)(A_ST + b_r * BSTR + b_c) * 4;

    float c[4][4][4];
#pragma unroll
    for (int mt = 0; mt < 4; ++mt)
#pragma unroll
        for (int nt = 0; nt < 4; ++nt)
#pragma unroll
            for (int i = 0; i < 4; ++i) c[mt][nt][i] = 0.0f;

    const int nkt = K / GBK;
    gemm_load_stage(a_dst, b_dst, Ap, Bp, K); CP_COMMIT();
    gemm_load_stage(a_dst + STAGE_FL * 4, b_dst + STAGE_FL * 4,
                    Ap + GBK, Bp + GBK, K); CP_COMMIT();

#pragma unroll 1
    for (int kt = 0; kt < nkt; ++kt) {
        if (kt + 1 < nkt) { CP_WAIT1(); } else { CP_WAIT0(); }
        __syncthreads();
        if (kt + 2 < nkt) {
            const uint32_t so = (uint32_t)((kt + 2) % 3) * STAGE_FL * 4;
            gemm_load_stage(a_dst + so, b_dst + so,
                            Ap + (kt + 2) * GBK, Bp + (kt + 2) * GBK, K);
        }
        CP_COMMIT();

        const uint32_t so = (uint32_t)(kt % 3) * STAGE_FL * 4;
#pragma unroll
        for (int ks = 0; ks < 4; ++ks) {
            uint32_t af[4][4];
#pragma unroll
            for (int mt = 0; mt < 4; ++mt) {
                ldsm_x4(af[mt], a_frag + so + (uint32_t)(mt * 16 * ASTR + ks * 8) * 4);
#pragma unroll
                for (int i = 0; i < 4; ++i) af[mt][i] = rna_tf32_u(af[mt][i]);
            }
            uint32_t bf[4][2];
#pragma unroll
            for (int p = 0; p < 2; ++p) {
                uint32_t t4[4];
                ldsm_x4(t4, b_frag + so + (uint32_t)(p * 16 * BSTR + ks * 8) * 4);
                bf[2 * p][0] = t4[0]; bf[2 * p][1] = t4[1];
                bf[2 * p + 1][0] = t4[2]; bf[2 * p + 1][1] = t4[3];
            }
#pragma unroll
            for (int mt = 0; mt < 4; ++mt)
#pragma unroll
                for (int nt = 0; nt < 4; ++nt)
                    mma_tf32(c[mt][nt], af[mt], bf[nt]);
        }
    }

    if (mode == 0) {
#pragma unroll
        for (int mt = 0; mt < 4; ++mt) {
            const int r0 = bm + wm * 64 + mt * 16 + g;
#pragma unroll
            for (int nt = 0; nt < 4; ++nt) {
                const int cc = bn + wn * 32 + nt * 8 + tig * 2;
                *(float2*)&C[(size_t)r0 * N + cc]       = make_float2(c[mt][nt][0], c[mt][nt][1]);
                *(float2*)&C[(size_t)(r0 + 8) * N + cc] = make_float2(c[mt][nt][2], c[mt][nt][3]);
            }
        }
        return;
    }

    // Fused K-rope / V^T epilogue: stage fp32 accumulators into smem tile.
    __syncthreads();
#pragma unroll
    for (int mt = 0; mt < 4; ++mt) {
        const int r0 = wm * 64 + mt * 16 + g;
#pragma unroll
        for (int nt = 0; nt < 4; ++nt) {
            const int cc = wn * 32 + nt * 8 + tig * 2;
            *(float2*)&sm[r0 * EP_STR + cc]       = make_float2(c[mt][nt][0], c[mt][nt][1]);
            *(float2*)&sm[(r0 + 8) * EP_STR + cc] = make_float2(c[mt][nt][2], c[mt][nt][3]);
        }
    }
    __syncthreads();

    if (mode == 1) {
        const int r    = tid >> 1;
        const int c0   = (tid & 1) * 64;
        const int srow = bm + r;
        const float sg = (c0 < 64) ? -1.0f : 1.0f;
#pragma unroll
        for (int i = 0; i < 16; ++i) {
            float4 x  = *(float4*)&sm[r * EP_STR + c0 + 4 * i];
            float4 p  = *(float4*)&sm[r * EP_STR + (c0 ^ 64) + 4 * i];
            float4 cv = *(const float4*)(cosp + (size_t)srow * HD + c0 + 4 * i);
            float4 sv = *(const float4*)(sinp + (size_t)srow * HD + c0 + 4 * i);
            float4 o;
            o.x = rna_tf32(x.x * cv.x + sg * p.x * sv.x);
            o.y = rna_tf32(x.y * cv.y + sg * p.y * sv.y);
            o.z = rna_tf32(x.z * cv.z + sg * p.z * sv.z);
            o.w = rna_tf32(x.w * cv.w + sg * p.w * sv.w);
            *(float4*)&dst[(size_t)srow * HD + c0 + 4 * i] = o;
        }
    } else {
        const int d  = tid >> 1;
        const int h2 = tid & 1;
#pragma unroll
        for (int i = 0; i < 16; ++i) {
            const int r = h2 * 64 + 4 * i;
            float4 o;
            o.x = rna_tf32(sm[(r + 0) * EP_STR + d]);
            o.y = rna_tf32(sm[(r + 1) * EP_STR + d]);
            o.z = rna_tf32(sm[(r + 2) * EP_STR + d]);
            o.w = rna_tf32(sm[(r + 3) * EP_STR + d]);
            *(float4*)&dst[(size_t)d * S_LEN + bm + r] = o;
        }
    }
}

// Plain GEMM wrapper (O-projection)
__global__ __launch_bounds__(256, 2) void gemm_mma(
    const float* __restrict__ A, const float* __restrict__ BT,
    float* __restrict__ C, int M, int N, int K)
{
    extern __shared__ float sm[];
    gemm_body(A, BT, C, N, K, blockIdx.y * GBM, blockIdx.x * GBN, sm,
              0, 0, 0, 0);
}

// Fused QKV GEMM (+rope-K/V^T epilogues) + wo-transpose tail fill.
#define QKV_GEMM_BLKS (48 * 16)      // 768
#define WO_T_BLKS     (128 * 32)     // 4096
__global__ __launch_bounds__(256, 2) void gemm_qkv_wo(
    const float* __restrict__ A, const float* __restrict__ BT,
    float* __restrict__ qkv, const float* __restrict__ wo,
    float* __restrict__ woT, const float* __restrict__ cosp,
    const float* __restrict__ sinp, float* __restrict__ kh,
    float* __restrict__ vt)
{
    extern __shared__ float sm[];
    const int bid = blockIdx.x;
    if (bid < QKV_GEMM_BLKS) {
        const int tm = bid / 48, tn = bid % 48;
        const int bm = tm * GBM, bn = tn * GBN;
        if (tn < 32) {
            gemm_body(A, BT, qkv, NQKV, HID, bm, bn, sm, 0, 0, 0, 0);
        } else if (tn < 40) {
            gemm_body(A, BT, qkv, NQKV, HID, bm, bn, sm, 1, cosp, sinp,
                      kh + (size_t)(tn - 32) * S_LEN * HD);
        } else {
            gemm_body(A, BT, qkv, NQKV, HID, bm, bn, sm, 2, 0, 0,
                      vt + (size_t)(tn - 40) * HD * S_LEN);
        }
    } else {
        const int l = bid - QKV_GEMM_BLKS;
        transpose_tile_rna(wo, woT, HID, NQ, (l % 128) * 32, (l / 128) * 128, sm);
    }
}

// ---------------------------------------------------------------------------
// Pre-pass: wq/wk/wv transposes only (hidden-state rounding now happens
// in-register inside the GEMM).
// ---------------------------------------------------------------------------
#define PREP_WQ_BLKS    (128 * 32)                // 4096
#define PREP_WK_BLKS    (32 * 32)                 // 1024
#define PREP_WV_BLKS    (32 * 32)                 // 1024
#define PREP_BLKS (PREP_WQ_BLKS + PREP_WK_BLKS + PREP_WV_BLKS)

__global__ __launch_bounds__(256) void prep_fused(
    const float* __restrict__ wq, const float* __restrict__ wk,
    const float* __restrict__ wv, float* __restrict__ wqkvT)
{
    __shared__ float tb[4 * 32 * 33];
    int bid = blockIdx.x;
    if (bid < PREP_WQ_BLKS) {
        transpose_tile_rna(wq, wqkvT, NQ, HID, (bid % 128) * 32, (bid / 128) * 128, tb);
        return;
    }
    bid -= PREP_WQ_BLKS;
    if (bid < PREP_WK_BLKS) {
        transpose_tile_rna(wk, wqkvT + (size_t)NQ * HID, NKVD, HID,
                           (bid % 32) * 32, (bid / 32) * 128, tb);
        return;
    }
    bid -= PREP_WK_BLKS;
    transpose_tile_rna(wv, wqkvT + (size_t)(NQ + NKVD) * HID, NKVD, HID,
                       (bid % 32) * 32, (bid / 32) * 128, tb);
}

// ---------------------------------------------------------------------------
// Flash attention, 2 CTAs/SM. BM=64, BN=64, 4 warps (16 q-rows each).
// No P smem (quad-shuffle A-fragments). Q rope fused in prologue.
// Base-2 softmax (log2e folded into QK scale; bare EX2 per element).
// 3 barriers/jt. smem: Q 64x132 + K 64x132 + VT 128x68 = 102400 B.
// ---------------------------------------------------------------------------
#define FB_QSTR 132
#define FB_KSTR 132
#define FB_VSTR 68
#define FB_QS 0
#define FB_KS (64 * FB_QSTR)
#define FB_VT (FB_KS + 64 * FB_KSTR)
#define FB_SMEM ((FB_VT + 128 * FB_VSTR) * 4)   // 102400 B

__global__ __launch_bounds__(128, 2) void flash_mma(
    const float* __restrict__ QKV, const float* __restrict__ cosp,
    const float* __restrict__ sinp, const float* __restrict__ Kh,
    const float* __restrict__ VT, float* __restrict__ O)
{
    extern __shared__ float sm[];
    const uint32_t sb = smem_u32(sm);

    const int tid  = threadIdx.x;
    const int lane = tid & 31;
    const int wid  = tid >> 5;
    const int g    = lane >> 2;
    const int tig  = lane & 3;
    const int qb   = gridDim.x - 1 - blockIdx.x;   // heavy CTAs first
    const int h    = blockIdx.y;
    const int kvh  = h >> 2;

    const float* Kbase  = Kh + (size_t)kvh * S_LEN * HD;
    const float* VTbase = VT + (size_t)kvh * HD * S_LEN;

    // Stage Q tile [64][128] with inline RoPE (reads raw projection)
#pragma unroll
    for (int j = 0; j < 16; ++j) {
        const int idx = tid + j * 128;
        const int r = idx >> 5, cb = (idx & 31) * 4;
        const int srow = qb * 64 + r;
        const float* qrow = QKV + (size_t)srow * NQKV + h * HD;
        float4 x  = *(const float4*)(qrow + cb);
        float4 p  = *(const float4*)(qrow + (cb ^ 64));
        float4 c4 = *(const float4*)(cosp + srow * HD + cb);
        float4 s4 = *(const float4*)(sinp + srow * HD + cb);
        const float sg = (cb < 64) ? -1.0f : 1.0f;
        sm[FB_QS + r * FB_QSTR + cb + 0] = rna_tf32(x.x * c4.x + sg * p.x * s4.x);
        sm[FB_QS + r * FB_QSTR + cb + 1] = rna_tf32(x.y * c4.y + sg * p.y * s4.y);
        sm[FB_QS + r * FB_QSTR + cb + 2] = rna_tf32(x.z * c4.z + sg * p.z * s4.z);
        sm[FB_QS + r * FB_QSTR + cb + 3] = rna_tf32(x.w * c4.w + sg * p.w * s4.w);
    }

    // ldmatrix per-lane bases
    const int rsel  = (lane & 7) + ((lane >> 3) & 1) * 8;
    const int csel  = (lane >> 4) * 4;
    const int brsel = ((lane >> 4) & 1) * 8 + (lane & 7);
    const int bcsel = ((lane >> 3) & 1) * 4;
    const uint32_t q_frag = sb + (uint32_t)(FB_QS + (wid * 16 + rsel) * FB_QSTR + csel) * 4;
    const uint32_t k_frag = sb + (uint32_t)(FB_KS + brsel * FB_KSTR + bcsel) * 4;
    const uint32_t v_frag = sb + (uint32_t)(FB_VT + brsel * FB_VSTR + bcsel) * 4;

    float s[8][4], o[16][4], m_i[2], l_i[2];
    m_i[0] = m_i[1] = -1e30f;
    l_i[0] = l_i[1] = 0.0f;
#pragma unroll
    for (int nt = 0; nt < 16; ++nt)
#pragma unroll
        for (int i = 0; i < 4; ++i) o[nt][i] = 0.0f;

    // Base-2 scale: 1/sqrt(128) * log2(e)
    const float sc = 0.08838834764831845f * 1.4426950408889634f;
    const int qrow0 = qb * 64 + wid * 16 + g;
    const int jtmax = qb;

    // Preload K(0) then V(0) as two separate cp.async groups.
#pragma unroll
    for (int j = 0; j < 16; ++j) {
        const int idx = tid + j * 128;
        const int r = idx >> 5, c = (idx & 31) * 4;
        cpasync16(sb + (uint32_t)(FB_KS + r * FB_KSTR + c) * 4,
                  Kbase + (size_t)r * HD + c);
    }
    CP_COMMIT();
#pragma unroll
    for (int j = 0; j < 16; ++j) {
        const int idx = tid + j * 128;
        const int d = idx >> 4, c = (idx & 15) * 4;
        cpasync16(sb + (uint32_t)(FB_VT + d * FB_VSTR + c) * 4,
                  VTbase + (size_t)d * S_LEN + c);
    }
    CP_COMMIT();

    for (int jt = 0; jt <= jtmax; ++jt) {
        CP_WAIT1();          // K(jt) landed (V(jt) may still be in flight)
        __syncthreads();

        // S = Q K^T  (16 x 64 per warp)
#pragma unroll
        for (int nt = 0; nt < 8; ++nt)
#pragma unroll
            for (int i = 0; i < 4; ++i) s[nt][i] = 0.0f;

#pragma unroll
        for (int ks = 0; ks < 16; ++ks) {
            uint32_t a[4];
            ldsm_x4(a, q_frag + ks * 32);
#pragma unroll
            for (int p = 0; p < 4; ++p) {
                uint32_t t4[4];
                ldsm_x4(t4, k_frag + (uint32_t)(p * 16 * FB_KSTR) * 4 + ks * 32);
                mma_tf32(s[2 * p],     a, t4);
                mma_tf32(s[2 * p + 1], a, t4 + 2);
            }
        }

        // Scale (base-2) + causal mask
        const int colb = jt * 64 + tig * 2;
#pragma unroll
        for (int nt = 0; nt < 8; ++nt) {
            const int c0 = colb + nt * 8, c1 = c0 + 1;
            s[nt][0] = (c0 > qrow0)     ? -1e30f : s[nt][0] * sc;
            s[nt][1] = (c1 > qrow0)     ? -1e30f : s[nt][1] * sc;
            s[nt][2] = (c0 > qrow0 + 8) ? -1e30f : s[nt][2] * sc;
            s[nt][3] = (c1 > qrow0 + 8) ? -1e30f : s[nt][3] * sc;
        }

        // Online softmax in base 2 (rows warp-private; quad reductions)
        float mx0 = -1e30f, mx1 = -1e30f;
#pragma unroll
        for (int nt = 0; nt < 8; ++nt) {
            mx0 = fmaxf(mx0, fmaxf(s[nt][0], s[nt][1]));
            mx1 = fmaxf(mx1, fmaxf(s[nt][2], s[nt][3]));
        }
        mx0 = fmaxf(mx0, __shfl_xor_sync(0xffffffffu, mx0, 1));
        mx0 = fmaxf(mx0, __shfl_xor_sync(0xffffffffu, mx0, 2));
        mx1 = fmaxf(mx1, __shfl_xor_sync(0xffffffffu, mx1, 1));
        mx1 = fmaxf(mx1, __shfl_xor_sync(0xffffffffu, mx1, 2));

        const float mn0 = fmaxf(m_i[0], mx0);
        const float mn1 = fmaxf(m_i[1], mx1);
        const float al0 = exp2f(m_i[0] - mn0);
        const float al1 = exp2f(m_i[1] - mn1);
        m_i[0] = mn0; m_i[1] = mn1;

        float rs0 = 0.0f, rs1 = 0.0f;
#pragma unroll
        for (int nt = 0; nt < 8; ++nt) {
            s[nt][0] = exp2f(s[nt][0] - mn0);
            s[nt][1] = exp2f(s[nt][1] - mn0);
            s[nt][2] = exp2f(s[nt][2] - mn1);
            s[nt][3] = exp2f(s[nt][3] - mn1);
            rs0 += s[nt][0] + s[nt][1];
            rs1 += s[nt][2] + s[nt][3];
        }
        rs0 += __shfl_xor_sync(0xffffffffu, rs0, 1);
        rs0 += __shfl_xor_sync(0xffffffffu, rs0, 2);
        rs1 += __shfl_xor_sync(0xffffffffu, rs1, 1);
        rs1 += __shfl_xor_sync(0xffffffffu, rs1, 2);
        l_i[0] = l_i[0] * al0 + rs0;
        l_i[1] = l_i[1] * al1 + rs1;
#pragma unroll
        for (int nt = 0; nt < 16; ++nt) {
            o[nt][0] *= al0; o[nt][1] *= al0;
            o[nt][2] *= al1; o[nt][3] *= al1;
        }

        CP_WAIT0();          // V(jt) landed (only group in flight here)
        __syncthreads();     // all warps see V; all warps past QK -> K reusable
        if (jt < jtmax) {    // stage K(jt+1); overlaps PV
#pragma unroll
            for (int j = 0; j < 16; ++j) {
                const int idx = tid + j * 128;
                const int r = idx >> 5, c = (idx & 31) * 4;
                cpasync16(sb + (uint32_t)(FB_KS + r * FB_KSTR + c) * 4,
                          Kbase + (size_t)((jt + 1) * 64 + r) * HD + c);
            }
        }
        CP_COMMIT();

        // O += P @ V. A-fragments from C-layout s[] via quad shuffles.
        const int qbase = lane & ~3;
        const int srcA  = qbase | (tig >> 1);
        const int srcB  = srcA + 2;
        const bool odd  = (tig & 1);
#pragma unroll
        for (int ks = 0; ks < 8; ++ks) {
            const float p0 = s[ks][0], p1 = s[ks][1];
            const float p2 = s[ks][2], p3 = s[ks][3];
            const float a0A = __shfl_sync(0xffffffffu, p0, srcA);
            const float a1A = __shfl_sync(0xffffffffu, p1, srcA);
            const float a2A = __shfl_sync(0xffffffffu, p2, srcA);
            const float a3A = __shfl_sync(0xffffffffu, p3, srcA);
            const float a0B = __shfl_sync(0xffffffffu, p0, srcB);
            const float a1B = __shfl_sync(0xffffffffu, p1, srcB);
            const float a2B = __shfl_sync(0xffffffffu, p2, srcB);
            const float a3B = __shfl_sync(0xffffffffu, p3, srcB);
            uint32_t a[4];
            a[0] = __float_as_uint(rna_tf32(odd ? a1A : a0A));
            a[1] = __float_as_uint(rna_tf32(odd ? a3A : a2A));
            a[2] = __float_as_uint(rna_tf32(odd ? a1B : a0B));
            a[3] = __float_as_uint(rna_tf32(odd ? a3B : a2B));
#pragma unroll
            for (int p = 0; p < 8; ++p) {
                uint32_t t4[4];
                ldsm_x4(t4, v_frag + (uint32_t)(p * 16 * FB_VSTR) * 4 + ks * 32);
                mma_tf32(o[2 * p],     a, t4);
                mma_tf32(o[2 * p + 1], a, t4 + 2);
            }
        }

        __syncthreads();     // all warps done reading V(jt)
        if (jt < jtmax) {    // stage V(jt+1); overlaps next QK
#pragma unroll
            for (int j = 0; j < 16; ++j) {
                const int idx = tid + j * 128;
                const int d = idx >> 4, c = (idx & 15) * 4;
                cpasync16(sb + (uint32_t)(FB_VT + d * FB_VSTR + c) * 4,
                          VTbase + (size_t)d * S_LEN + (jt + 1) * 64 + c);
            }
        }
        CP_COMMIT();
    }

    // Epilogue: normalize, tf32-round, write [S][NQ]
    const float inv0 = 1.0f / l_i[0];
    const float inv1 = 1.0f / l_i[1];
    float* Op = O + (size_t)qrow0 * NQ + h * HD;
#pragma unroll
    for (int nt = 0; nt < 16; ++nt) {
        const int cc = nt * 8 + tig * 2;
        *(float2*)&Op[cc] =
            make_float2(rna_tf32(o[nt][0] * inv0), rna_tf32(o[nt][1] * inv0));
        *(float2*)&Op[(size_t)8 * NQ + cc] =
            make_float2(rna_tf32(o[nt][2] * inv1), rna_tf32(o[nt][3] * inv1));
    }
}

// ---------------------------------------------------------------------------
// Launch. Inputs: 0 hidden_states, 1 attention_mask (unused), 2 wq, 3 wk,
// 4 wv, 5 wo, 6 cos, 7 sin.
// Four launches: prep, qkv-gemm(+rope/vt epilogue)+wo-transpose, flash, O-proj.
// ---------------------------------------------------------------------------
extern "C" void kernel_launch(void* const* d_in, const int* in_sizes, int n_in,
                              void* d_out, int out_size)
{
    (void)in_sizes; (void)n_in; (void)out_size;
    const float* hs = (const float*)d_in[0];
    const float* wq = (const float*)d_in[2];
    const float* wk = (const float*)d_in[3];
    const float* wv = (const float*)d_in[4];
    const float* wo = (const float*)d_in[5];
    const float* cs = (const float*)d_in[6];
    const float* sn = (const float*)d_in[7];
    float* out = (float*)d_out;

    float *wqkvT, *woT, *qkv, *kh, *vt, *ao;
    cudaGetSymbolAddress((void**)&wqkvT, g_wqkvT);
    cudaGetSymbolAddress((void**)&woT,   g_woT);
    cudaGetSymbolAddress((void**)&qkv,   g_qkv);
    cudaGetSymbolAddress((void**)&kh,    g_kh);
    cudaGetSymbolAddress((void**)&vt,    g_vt);
    cudaGetSymbolAddress((void**)&ao,    g_ao);

    cudaFuncSetAttribute(gemm_mma,    cudaFuncAttributeMaxDynamicSharedMemorySize, GEMM_SMEM);
    cudaFuncSetAttribute(gemm_qkv_wo, cudaFuncAttributeMaxDynamicSharedMemorySize, GEMM_SMEM);
    cudaFuncSetAttribute(flash_mma,   cudaFuncAttributeMaxDynamicSharedMemorySize, FB_SMEM);

    // #1: weight transposes (hidden-state rounding now in-register in GEMM)
    prep_fused<<<PREP_BLKS, 256>>>(wq, wk, wv, wqkvT);

    // #2: QKV GEMM (raw hs A, in-register rna) + rope-K/V^T epilogues
    //     + wo-transpose tail
    gemm_qkv_wo<<<QKV_GEMM_BLKS + WO_T_BLKS, 256, GEMM_SMEM>>>(
        hs, wqkvT, qkv, wo, woT, cs, sn, kh, vt);

    // #3: flash attention (2 CTAs/SM, BM=64, shuffle-P, fused Q-rope,
    //     base-2 softmax)
    flash_mma<<<dim3(S_LEN / 64, NH), 128, FB_SMEM>>>(qkv, cs, sn, kh, vt, ao);

    // #4: output projection (tf32 — the proven ceiling)
    gemm_mma<<<dim3(HID / GBN, S_LEN / GBM), 256, GEMM_SMEM>>>(ao, woT, out, S_LEN, HID, NQ);
}

// round 16
// speedup vs baseline: 1.2799x; 1.0658x over previous
#include <cuda_runtime.h>
#include <cuda_bf16.h>
#include <math.h>
#include <stdint.h>

// Problem constants
#define S_LEN 2048
#define HID   4096
#define NH    32
#define NKV   8
#define HD    128
#define NQ    (NH * HD)    // 4096
#define NKVD  (NKV * HD)   // 1024
#define NQKV  (NQ + 2 * NKVD)  // 6144

// ---------------------------------------------------------------------------
// Scratch (static device arrays; no cudaMalloc allowed)
// ---------------------------------------------------------------------------
__device__ float g_hsr  [S_LEN * HID];     // hidden states, tf32-rounded
__device__ float g_wqkvT[NQKV * HID];      // [wq^T ; wk^T ; wv^T]  [6144][4096]
__device__ float g_woT  [HID * NQ];        // wo^T  [4096][4096]
__device__ float g_qkv  [S_LEN * NQKV];    // QKV projection (Q region used)
__device__ float g_kh   [S_LEN * NKVD];    // K rope, head-major [NKV][S][HD]
__device__ float g_vt   [S_LEN * NKVD];    // V^T head-major [NKV][HD][S]
__device__ float g_ao   [S_LEN * NQ];      // attention out [S][4096]

// ---------------------------------------------------------------------------
// Helpers
// ---------------------------------------------------------------------------
__device__ __forceinline__ uint32_t smem_u32(const void* p) {
    uint32_t a;
    asm("{ .reg .u64 t; cvta.to.shared.u64 t, %1; cvt.u32.u64 %0, t; }"
        : "=r"(a) : "l"(p));
    return a;
}
__device__ __forceinline__ float rna_tf32(float v) {
    uint32_t o;
    asm("cvt.rna.tf32.f32 %0, %1;" : "=r"(o) : "f"(v));
    return __uint_as_float(o);
}
__device__ __forceinline__ void mma_tf32(float* c, const uint32_t* a, const uint32_t* b) {
    asm("mma.sync.aligned.m16n8k8.row.col.f32.tf32.tf32.f32 "
        "{%0,%1,%2,%3}, {%4,%5,%6,%7}, {%8,%9}, {%0,%1,%2,%3};"
        : "+f"(c[0]), "+f"(c[1]), "+f"(c[2]), "+f"(c[3])
        : "r"(a[0]), "r"(a[1]), "r"(a[2]), "r"(a[3]), "r"(b[0]), "r"(b[1]));
}
__device__ __forceinline__ void ldsm_x4(uint32_t* r, uint32_t saddr) {
    asm volatile("ldmatrix.sync.aligned.m8n8.x4.shared.b16 {%0,%1,%2,%3}, [%4];"
        : "=r"(r[0]), "=r"(r[1]), "=r"(r[2]), "=r"(r[3]) : "r"(saddr));
}
__device__ __forceinline__ void cpasync16(uint32_t dst, const void* src) {
    asm volatile("cp.async.cg.shared.global [%0], [%1], 16;" :: "r"(dst), "l"(src));
}
#define CP_COMMIT()  asm volatile("cp.async.commit_group;" ::: "memory")
#define CP_WAIT0()   asm volatile("cp.async.wait_group 0;" ::: "memory")
#define CP_WAIT1()   asm volatile("cp.async.wait_group 1;" ::: "memory")

// ---------------------------------------------------------------------------
// Shared transpose tile (32n x 128k) + tf32 round: out[n][k] = rna(in[k][n]).
// ---------------------------------------------------------------------------
__device__ __forceinline__ void transpose_tile_rna(
    const float* __restrict__ in, float* __restrict__ out,
    int ldin, int ldout, int n0, int k0, float* tb)
{
    const int tx = threadIdx.x & 31;
    const int wy = threadIdx.x >> 5;  // 0..7
#pragma unroll
    for (int tt = 0; tt < 4; ++tt)
#pragma unroll
        for (int j = 0; j < 4; ++j)
            tb[(tt * 32 + wy + 8 * j) * 33 + tx] =
                in[(size_t)(k0 + tt * 32 + wy + 8 * j) * ldin + n0 + tx];
    __syncthreads();
#pragma unroll
    for (int tt = 0; tt < 4; ++tt)
#pragma unroll
        for (int j = 0; j < 4; ++j)
            out[(size_t)(n0 + wy + 8 * j) * ldout + k0 + tt * 32 + tx] =
                rna_tf32(tb[(tt * 32 + tx) * 33 + wy + 8 * j]);
}

// ---------------------------------------------------------------------------
// tf32 mma GEMM body (R13 verbatim — no in-register CVTs; at the measured
// 161 TF/s mma.sync dispatch ceiling, do not touch). 128x128 tile, 8 warps
// of 64x32 warp tiles, BK=32, 3-stage cp.async, ldmatrix, 2 CTAs/SM.
// Epilogue modes: 0 plain, 1 rope-K, 2 V^T.
// ---------------------------------------------------------------------------
#define GBM 128
#define GBN 128
#define GBK 32
#define ASTR 36
#define BSTR 36
#define A_ST (128 * ASTR)
#define B_ST (128 * BSTR)
#define STAGE_FL (A_ST + B_ST)
#define GEMM_SMEM (3 * STAGE_FL * 4)   // 110592 B
#define EP_STR 132

__device__ __forceinline__ void gemm_load_stage(
    uint32_t a_dst, uint32_t b_dst, const float* ap, const float* bp, int K)
{
#pragma unroll
    for (int i = 0; i < 4; ++i)
        cpasync16(a_dst + i * 32 * ASTR * 4, ap + (size_t)i * 32 * K);
#pragma unroll
    for (int i = 0; i < 4; ++i)
        cpasync16(b_dst + i * 32 * BSTR * 4, bp + (size_t)i * 32 * K);
}

__device__ __forceinline__ void gemm_body(
    const float* __restrict__ A, const float* __restrict__ BT,
    float* __restrict__ C, int N, int K, int bm, int bn, float* sm,
    int mode, const float* __restrict__ cosp, const float* __restrict__ sinp,
    float* __restrict__ dst)
{
    const uint32_t sb = smem_u32(sm);
    const int tid  = threadIdx.x;
    const int lane = tid & 31;
    const int wid  = tid >> 5;
    const int wm   = wid >> 2;
    const int wn   = wid & 3;
    const int g    = lane >> 2;
    const int tig  = lane & 3;

    const int lrow = tid >> 3;
    const int lcol = (tid & 7) * 4;
    const float* Ap = A  + (size_t)(bm + lrow) * K + lcol;
    const float* Bp = BT + (size_t)(bn + lrow) * K + lcol;
    const uint32_t a_dst = sb + (uint32_t)(lrow * ASTR + lcol) * 4;
    const uint32_t b_dst = sb + (uint32_t)(A_ST + lrow * BSTR + lcol) * 4;

    const int a_r = wm * 64 + (lane & 7) + ((lane >> 3) & 1) * 8;
    const int a_c = (lane >> 4) * 4;
    const uint32_t a_frag = sb + (uint32_t)(a_r * ASTR + a_c) * 4;
    const int b_r = wn * 32 + ((lane >> 4) & 1) * 8 + (lane & 7);
    const int b_c = ((lane >> 3) & 1) * 4;
    const uint32_t b_frag = sb + (uint32_t)(A_ST + b_r * BSTR + b_c) * 4;

    float c[4][4][4];
#pragma unroll
    for (int mt = 0; mt < 4; ++mt)
#pragma unroll
        for (int nt = 0; nt < 4; ++nt)
#pragma unroll
            for (int i = 0; i < 4; ++i) c[mt][nt][i] = 0.0f;

    const int nkt = K / GBK;
    gemm_load_stage(a_dst, b_dst, Ap, Bp, K); CP_COMMIT();
    gemm_load_stage(a_dst + STAGE_FL * 4, b_dst + STAGE_FL * 4,
                    Ap + GBK, Bp + GBK, K); CP_COMMIT();

#pragma unroll 1
    for (int kt = 0; kt < nkt; ++kt) {
        if (kt + 1 < nkt) { CP_WAIT1(); } else { CP_WAIT0(); }
        __syncthreads();
        if (kt + 2 < nkt) {
            const uint32_t so = (uint32_t)((kt + 2) % 3) * STAGE_FL * 4;
            gemm_load_stage(a_dst + so, b_dst + so,
                            Ap + (kt + 2) * GBK, Bp + (kt + 2) * GBK, K);
        }
        CP_COMMIT();

        const uint32_t so = (uint32_t)(kt % 3) * STAGE_FL * 4;
#pragma unroll
        for (int ks = 0; ks < 4; ++ks) {
            uint32_t af[4][4];
#pragma unroll
            for (int mt = 0; mt < 4; ++mt)
                ldsm_x4(af[mt], a_frag + so + (uint32_t)(mt * 16 * ASTR + ks * 8) * 4);
            uint32_t bf[4][2];
#pragma unroll
            for (int p = 0; p < 2; ++p) {
                uint32_t t4[4];
                ldsm_x4(t4, b_frag + so + (uint32_t)(p * 16 * BSTR + ks * 8) * 4);
                bf[2 * p][0] = t4[0]; bf[2 * p][1] = t4[1];
                bf[2 * p + 1][0] = t4[2]; bf[2 * p + 1][1] = t4[3];
            }
#pragma unroll
            for (int mt = 0; mt < 4; ++mt)
#pragma unroll
                for (int nt = 0; nt < 4; ++nt)
                    mma_tf32(c[mt][nt], af[mt], bf[nt]);
        }
    }

    if (mode == 0) {
#pragma unroll
        for (int mt = 0; mt < 4; ++mt) {
            const int r0 = bm + wm * 64 + mt * 16 + g;
#pragma unroll
            for (int nt = 0; nt < 4; ++nt) {
                const int cc = bn + wn * 32 + nt * 8 + tig * 2;
                *(float2*)&C[(size_t)r0 * N + cc]       = make_float2(c[mt][nt][0], c[mt][nt][1]);
                *(float2*)&C[(size_t)(r0 + 8) * N + cc] = make_float2(c[mt][nt][2], c[mt][nt][3]);
            }
        }
        return;
    }

    // Fused K-rope / V^T epilogue: stage fp32 accumulators into smem tile.
    __syncthreads();
#pragma unroll
    for (int mt = 0; mt < 4; ++mt) {
        const int r0 = wm * 64 + mt * 16 + g;
#pragma unroll
        for (int nt = 0; nt < 4; ++nt) {
            const int cc = wn * 32 + nt * 8 + tig * 2;
            *(float2*)&sm[r0 * EP_STR + cc]       = make_float2(c[mt][nt][0], c[mt][nt][1]);
            *(float2*)&sm[(r0 + 8) * EP_STR + cc] = make_float2(c[mt][nt][2], c[mt][nt][3]);
        }
    }
    __syncthreads();

    if (mode == 1) {
        const int r    = tid >> 1;
        const int c0   = (tid & 1) * 64;
        const int srow = bm + r;
        const float sg = (c0 < 64) ? -1.0f : 1.0f;
#pragma unroll
        for (int i = 0; i < 16; ++i) {
            float4 x  = *(float4*)&sm[r * EP_STR + c0 + 4 * i];
            float4 p  = *(float4*)&sm[r * EP_STR + (c0 ^ 64) + 4 * i];
            float4 cv = *(const float4*)(cosp + (size_t)srow * HD + c0 + 4 * i);
            float4 sv = *(const float4*)(sinp + (size_t)srow * HD + c0 + 4 * i);
            float4 o;
            o.x = rna_tf32(x.x * cv.x + sg * p.x * sv.x);
            o.y = rna_tf32(x.y * cv.y + sg * p.y * sv.y);
            o.z = rna_tf32(x.z * cv.z + sg * p.z * sv.z);
            o.w = rna_tf32(x.w * cv.w + sg * p.w * sv.w);
            *(float4*)&dst[(size_t)srow * HD + c0 + 4 * i] = o;
        }
    } else {
        const int d  = tid >> 1;
        const int h2 = tid & 1;
#pragma unroll
        for (int i = 0; i < 16; ++i) {
            const int r = h2 * 64 + 4 * i;
            float4 o;
            o.x = rna_tf32(sm[(r + 0) * EP_STR + d]);
            o.y = rna_tf32(sm[(r + 1) * EP_STR + d]);
            o.z = rna_tf32(sm[(r + 2) * EP_STR + d]);
            o.w = rna_tf32(sm[(r + 3) * EP_STR + d]);
            *(float4*)&dst[(size_t)d * S_LEN + bm + r] = o;
        }
    }
}

// Plain GEMM wrapper (O-projection)
__global__ __launch_bounds__(256, 2) void gemm_mma(
    const float* __restrict__ A, const float* __restrict__ BT,
    float* __restrict__ C, int M, int N, int K)
{
    extern __shared__ float sm[];
    gemm_body(A, BT, C, N, K, blockIdx.y * GBM, blockIdx.x * GBN, sm,
              0, 0, 0, 0);
}

// Fused QKV GEMM (+rope-K/V^T epilogues) + wo-transpose tail fill.
#define QKV_GEMM_BLKS (48 * 16)      // 768
#define WO_T_BLKS     (128 * 32)     // 4096
__global__ __launch_bounds__(256, 2) void gemm_qkv_wo(
    const float* __restrict__ A, const float* __restrict__ BT,
    float* __restrict__ qkv, const float* __restrict__ wo,
    float* __restrict__ woT, const float* __restrict__ cosp,
    const float* __restrict__ sinp, float* __restrict__ kh,
    float* __restrict__ vt)
{
    extern __shared__ float sm[];
    const int bid = blockIdx.x;
    if (bid < QKV_GEMM_BLKS) {
        const int tm = bid / 48, tn = bid % 48;
        const int bm = tm * GBM, bn = tn * GBN;
        if (tn < 32) {
            gemm_body(A, BT, qkv, NQKV, HID, bm, bn, sm, 0, 0, 0, 0);
        } else if (tn < 40) {
            gemm_body(A, BT, qkv, NQKV, HID, bm, bn, sm, 1, cosp, sinp,
                      kh + (size_t)(tn - 32) * S_LEN * HD);
        } else {
            gemm_body(A, BT, qkv, NQKV, HID, bm, bn, sm, 2, 0, 0,
                      vt + (size_t)(tn - 40) * HD * S_LEN);
        }
    } else {
        const int l = bid - QKV_GEMM_BLKS;
        transpose_tile_rna(wo, woT, HID, NQ, (l % 128) * 32, (l / 128) * 128, sm);
    }
}

// ---------------------------------------------------------------------------
// Fused pre-pass: round(hidden) + wq/wk/wv transposes, one launch (R13).
// ---------------------------------------------------------------------------
#define PREP_ROUND_BLKS (S_LEN * HID / 4 / 256)   // 8192
#define PREP_WQ_BLKS    (128 * 32)                // 4096
#define PREP_WK_BLKS    (32 * 32)                 // 1024
#define PREP_WV_BLKS    (32 * 32)                 // 1024
#define PREP_BLKS (PREP_ROUND_BLKS + PREP_WQ_BLKS + PREP_WK_BLKS + PREP_WV_BLKS)

__global__ __launch_bounds__(256) void prep_fused(
    const float* __restrict__ hs, const float* __restrict__ wq,
    const float* __restrict__ wk, const float* __restrict__ wv,
    float* __restrict__ hsr, float* __restrict__ wqkvT)
{
    __shared__ float tb[4 * 32 * 33];
    int bid = blockIdx.x;
    if (bid < PREP_ROUND_BLKS) {
        const int i = bid * 256 + threadIdx.x;
        float4 v = ((const float4*)hs)[i];
        v.x = rna_tf32(v.x); v.y = rna_tf32(v.y);
        v.z = rna_tf32(v.z); v.w = rna_tf32(v.w);
        ((float4*)hsr)[i] = v;
        return;
    }
    bid -= PREP_ROUND_BLKS;
    if (bid < PREP_WQ_BLKS) {
        transpose_tile_rna(wq, wqkvT, NQ, HID, (bid % 128) * 32, (bid / 128) * 128, tb);
        return;
    }
    bid -= PREP_WQ_BLKS;
    if (bid < PREP_WK_BLKS) {
        transpose_tile_rna(wk, wqkvT + (size_t)NQ * HID, NKVD, HID,
                           (bid % 32) * 32, (bid / 32) * 128, tb);
        return;
    }
    bid -= PREP_WK_BLKS;
    transpose_tile_rna(wv, wqkvT + (size_t)(NQ + NKVD) * HID, NKVD, HID,
                       (bid % 32) * 32, (bid / 32) * 128, tb);
}

// ---------------------------------------------------------------------------
// Flash attention, 2 CTAs/SM. BM=64, BN=64, 4 warps (16 q-rows each).
// No P smem (quad-shuffle A-fragments). Q rope fused in prologue.
// Base-2 softmax (log2e folded into QK scale). 3 barriers/jt.
// smem: Q 64x132 + K 64x132 + VT 128x68 = 102400 B -> 2 CTAs/SM.
// ---------------------------------------------------------------------------
#define FB_QSTR 132
#define FB_KSTR 132
#define FB_VSTR 68
#define FB_QS 0
#define FB_KS (64 * FB_QSTR)
#define FB_VT (FB_KS + 64 * FB_KSTR)
#define FB_SMEM ((FB_VT + 128 * FB_VSTR) * 4)   // 102400 B

__global__ __launch_bounds__(128, 2) void flash_mma(
    const float* __restrict__ QKV, const float* __restrict__ cosp,
    const float* __restrict__ sinp, const float* __restrict__ Kh,
    const float* __restrict__ VT, float* __restrict__ O)
{
    extern __shared__ float sm[];
    const uint32_t sb = smem_u32(sm);

    const int tid  = threadIdx.x;
    const int lane = tid & 31;
    const int wid  = tid >> 5;
    const int g    = lane >> 2;
    const int tig  = lane & 3;
    const int qb   = gridDim.x - 1 - blockIdx.x;   // heavy CTAs first
    const int h    = blockIdx.y;
    const int kvh  = h >> 2;

    const float* Kbase  = Kh + (size_t)kvh * S_LEN * HD;
    const float* VTbase = VT + (size_t)kvh * HD * S_LEN;

    // Stage Q tile [64][128] with inline RoPE (reads raw projection)
#pragma unroll
    for (int j = 0; j < 16; ++j) {
        const int idx = tid + j * 128;
        const int r = idx >> 5, cb = (idx & 31) * 4;
        const int srow = qb * 64 + r;
        const float* qrow = QKV + (size_t)srow * NQKV + h * HD;
        float4 x  = *(const float4*)(qrow + cb);
        float4 p  = *(const float4*)(qrow + (cb ^ 64));
        float4 c4 = *(const float4*)(cosp + srow * HD + cb);
        float4 s4 = *(const float4*)(sinp + srow * HD + cb);
        const float sg = (cb < 64) ? -1.0f : 1.0f;
        sm[FB_QS + r * FB_QSTR + cb + 0] = rna_tf32(x.x * c4.x + sg * p.x * s4.x);
        sm[FB_QS + r * FB_QSTR + cb + 1] = rna_tf32(x.y * c4.y + sg * p.y * s4.y);
        sm[FB_QS + r * FB_QSTR + cb + 2] = rna_tf32(x.z * c4.z + sg * p.z * s4.z);
        sm[FB_QS + r * FB_QSTR + cb + 3] = rna_tf32(x.w * c4.w + sg * p.w * s4.w);
    }

    // ldmatrix per-lane bases
    const int rsel  = (lane & 7) + ((lane >> 3) & 1) * 8;
    const int csel  = (lane >> 4) * 4;
    const int brsel = ((lane >> 4) & 1) * 8 + (lane & 7);
    const int bcsel = ((lane >> 3) & 1) * 4;
    const uint32_t q_frag = sb + (uint32_t)(FB_QS + (wid * 16 + rsel) * FB_QSTR + csel) * 4;
    const uint32_t k_frag = sb + (uint32_t)(FB_KS + brsel * FB_KSTR + bcsel) * 4;
    const uint32_t v_frag = sb + (uint32_t)(FB_VT + brsel * FB_VSTR + bcsel) * 4;

    float s[8][4], o[16][4], m_i[2], l_i[2];
    m_i[0] = m_i[1] = -1e30f;
    l_i[0] = l_i[1] = 0.0f;
#pragma unroll
    for (int nt = 0; nt < 16; ++nt)
#pragma unroll
        for (int i = 0; i < 4; ++i) o[nt][i] = 0.0f;

    // Base-2 scale: 1/sqrt(128) * log2(e)
    const float sc = 0.08838834764831845f * 1.4426950408889634f;
    const int qrow0 = qb * 64 + wid * 16 + g;
    const int jtmax = qb;

    // Preload K(0) then V(0) as two separate cp.async groups.
#pragma unroll
    for (int j = 0; j < 16; ++j) {
        const int idx = tid + j * 128;
        const int r = idx >> 5, c = (idx & 31) * 4;
        cpasync16(sb + (uint32_t)(FB_KS + r * FB_KSTR + c) * 4,
                  Kbase + (size_t)r * HD + c);
    }
    CP_COMMIT();
#pragma unroll
    for (int j = 0; j < 16; ++j) {
        const int idx = tid + j * 128;
        const int d = idx >> 4, c = (idx & 15) * 4;
        cpasync16(sb + (uint32_t)(FB_VT + d * FB_VSTR + c) * 4,
                  VTbase + (size_t)d * S_LEN + c);
    }
    CP_COMMIT();

    for (int jt = 0; jt <= jtmax; ++jt) {
        CP_WAIT1();          // K(jt) landed (V(jt) may still be in flight)
        __syncthreads();

        // S = Q K^T  (16 x 64 per warp)
#pragma unroll
        for (int nt = 0; nt < 8; ++nt)
#pragma unroll
            for (int i = 0; i < 4; ++i) s[nt][i] = 0.0f;

#pragma unroll
        for (int ks = 0; ks < 16; ++ks) {
            uint32_t a[4];
            ldsm_x4(a, q_frag + ks * 32);
#pragma unroll
            for (int p = 0; p < 4; ++p) {
                uint32_t t4[4];
                ldsm_x4(t4, k_frag + (uint32_t)(p * 16 * FB_KSTR) * 4 + ks * 32);
                mma_tf32(s[2 * p],     a, t4);
                mma_tf32(s[2 * p + 1], a, t4 + 2);
            }
        }

        // Scale (base-2) + causal mask
        const int colb = jt * 64 + tig * 2;
#pragma unroll
        for (int nt = 0; nt < 8; ++nt) {
            const int c0 = colb + nt * 8, c1 = c0 + 1;
            s[nt][0] = (c0 > qrow0)     ? -1e30f : s[nt][0] * sc;
            s[nt][1] = (c1 > qrow0)     ? -1e30f : s[nt][1] * sc;
            s[nt][2] = (c0 > qrow0 + 8) ? -1e30f : s[nt][2] * sc;
            s[nt][3] = (c1 > qrow0 + 8) ? -1e30f : s[nt][3] * sc;
        }

        // Online softmax in base 2 (rows warp-private; quad reductions)
        float mx0 = -1e30f, mx1 = -1e30f;
#pragma unroll
        for (int nt = 0; nt < 8; ++nt) {
            mx0 = fmaxf(mx0, fmaxf(s[nt][0], s[nt][1]));
            mx1 = fmaxf(mx1, fmaxf(s[nt][2], s[nt][3]));
        }
        mx0 = fmaxf(mx0, __shfl_xor_sync(0xffffffffu, mx0, 1));
        mx0 = fmaxf(mx0, __shfl_xor_sync(0xffffffffu, mx0, 2));
        mx1 = fmaxf(mx1, __shfl_xor_sync(0xffffffffu, mx1, 1));
        mx1 = fmaxf(mx1, __shfl_xor_sync(0xffffffffu, mx1, 2));

        const float mn0 = fmaxf(m_i[0], mx0);
        const float mn1 = fmaxf(m_i[1], mx1);
        const float al0 = exp2f(m_i[0] - mn0);
        const float al1 = exp2f(m_i[1] - mn1);
        m_i[0] = mn0; m_i[1] = mn1;

        float rs0 = 0.0f, rs1 = 0.0f;
#pragma unroll
        for (int nt = 0; nt < 8; ++nt) {
            s[nt][0] = exp2f(s[nt][0] - mn0);
            s[nt][1] = exp2f(s[nt][1] - mn0);
            s[nt][2] = exp2f(s[nt][2] - mn1);
            s[nt][3] = exp2f(s[nt][3] - mn1);
            rs0 += s[nt][0] + s[nt][1];
            rs1 += s[nt][2] + s[nt][3];
        }
        rs0 += __shfl_xor_sync(0xffffffffu, rs0, 1);
        rs0 += __shfl_xor_sync(0xffffffffu, rs0, 2);
        rs1 += __shfl_xor_sync(0xffffffffu, rs1, 1);
        rs1 += __shfl_xor_sync(0xffffffffu, rs1, 2);
        l_i[0] = l_i[0] * al0 + rs0;
        l_i[1] = l_i[1] * al1 + rs1;
#pragma unroll
        for (int nt = 0; nt < 16; ++nt) {
            o[nt][0] *= al0; o[nt][1] *= al0;
            o[nt][2] *= al1; o[nt][3] *= al1;
        }

        CP_WAIT0();          // V(jt) landed (only group in flight here)
        __syncthreads();     // all warps see V; all warps past QK -> K reusable
        if (jt < jtmax) {    // stage K(jt+1); overlaps PV
#pragma unroll
            for (int j = 0; j < 16; ++j) {
                const int idx = tid + j * 128;
                const int r = idx >> 5, c = (idx & 31) * 4;
                cpasync16(sb + (uint32_t)(FB_KS + r * FB_KSTR + c) * 4,
                          Kbase + (size_t)((jt + 1) * 64 + r) * HD + c);
            }
        }
        CP_COMMIT();

        // O += P @ V. A-fragments from C-layout s[] via quad shuffles.
        const int qbase = lane & ~3;
        const int srcA  = qbase | (tig >> 1);
        const int srcB  = srcA + 2;
        const bool odd  = (tig & 1);
#pragma unroll
        for (int ks = 0; ks < 8; ++ks) {
            const float p0 = s[ks][0], p1 = s[ks][1];
            const float p2 = s[ks][2], p3 = s[ks][3];
            const float a0A = __shfl_sync(0xffffffffu, p0, srcA);
            const float a1A = __shfl_sync(0xffffffffu, p1, srcA);
            const float a2A = __shfl_sync(0xffffffffu, p2, srcA);
            const float a3A = __shfl_sync(0xffffffffu, p3, srcA);
            const float a0B = __shfl_sync(0xffffffffu, p0, srcB);
            const float a1B = __shfl_sync(0xffffffffu, p1, srcB);
            const float a2B = __shfl_sync(0xffffffffu, p2, srcB);
            const float a3B = __shfl_sync(0xffffffffu, p3, srcB);
            uint32_t a[4];
            a[0] = __float_as_uint(rna_tf32(odd ? a1A : a0A));
            a[1] = __float_as_uint(rna_tf32(odd ? a3A : a2A));
            a[2] = __float_as_uint(rna_tf32(odd ? a1B : a0B));
            a[3] = __float_as_uint(rna_tf32(odd ? a3B : a2B));
#pragma unroll
            for (int p = 0; p < 8; ++p) {
                uint32_t t4[4];
                ldsm_x4(t4, v_frag + (uint32_t)(p * 16 * FB_VSTR) * 4 + ks * 32);
                mma_tf32(o[2 * p],     a, t4);
                mma_tf32(o[2 * p + 1], a, t4 + 2);
            }
        }

        __syncthreads();     // all warps done reading V(jt)
        if (jt < jtmax) {    // stage V(jt+1); overlaps next QK
#pragma unroll
            for (int j = 0; j < 16; ++j) {
                const int idx = tid + j * 128;
                const int d = idx >> 4, c = (idx & 15) * 4;
                cpasync16(sb + (uint32_t)(FB_VT + d * FB_VSTR + c) * 4,
                          VTbase + (size_t)d * S_LEN + (jt + 1) * 64 + c);
            }
        }
        CP_COMMIT();
    }

    // Epilogue: normalize, tf32-round, write [S][NQ]
    const float inv0 = 1.0f / l_i[0];
    const float inv1 = 1.0f / l_i[1];
    float* Op = O + (size_t)qrow0 * NQ + h * HD;
#pragma unroll
    for (int nt = 0; nt < 16; ++nt) {
        const int cc = nt * 8 + tig * 2;
        *(float2*)&Op[cc] =
            make_float2(rna_tf32(o[nt][0] * inv0), rna_tf32(o[nt][1] * inv0));
        *(float2*)&Op[(size_t)8 * NQ + cc] =
            make_float2(rna_tf32(o[nt][2] * inv1), rna_tf32(o[nt][3] * inv1));
    }
}

// ---------------------------------------------------------------------------
// Launch. Inputs: 0 hidden_states, 1 attention_mask (unused), 2 wq, 3 wk,
// 4 wv, 5 wo, 6 cos, 7 sin.
// Four launches: prep, qkv-gemm(+rope/vt epilogue)+wo-transpose, flash, O-proj.
// ---------------------------------------------------------------------------
extern "C" void kernel_launch(void* const* d_in, const int* in_sizes, int n_in,
                              void* d_out, int out_size)
{
    (void)in_sizes; (void)n_in; (void)out_size;
    const float* hs = (const float*)d_in[0];
    const float* wq = (const float*)d_in[2];
    const float* wk = (const float*)d_in[3];
    const float* wv = (const float*)d_in[4];
    const float* wo = (const float*)d_in[5];
    const float* cs = (const float*)d_in[6];
    const float* sn = (const float*)d_in[7];
    float* out = (float*)d_out;

    float *hsr, *wqkvT, *woT, *qkv, *kh, *vt, *ao;
    cudaGetSymbolAddress((void**)&hsr,   g_hsr);
    cudaGetSymbolAddress((void**)&wqkvT, g_wqkvT);
    cudaGetSymbolAddress((void**)&woT,   g_woT);
    cudaGetSymbolAddress((void**)&qkv,   g_qkv);
    cudaGetSymbolAddress((void**)&kh,    g_kh);
    cudaGetSymbolAddress((void**)&vt,    g_vt);
    cudaGetSymbolAddress((void**)&ao,    g_ao);

    cudaFuncSetAttribute(gemm_mma,    cudaFuncAttributeMaxDynamicSharedMemorySize, GEMM_SMEM);
    cudaFuncSetAttribute(gemm_qkv_wo, cudaFuncAttributeMaxDynamicSharedMemorySize, GEMM_SMEM);
    cudaFuncSetAttribute(flash_mma,   cudaFuncAttributeMaxDynamicSharedMemorySize, FB_SMEM);

    // #1: fused pre-pass (round + wq/wk/wv transposes) — R13 configuration
    prep_fused<<<PREP_BLKS, 256>>>(hs, wq, wk, wv, hsr, wqkvT);

    // #2: QKV GEMM (pre-rounded A) + rope-K/V^T epilogues + wo-transpose tail
    gemm_qkv_wo<<<QKV_GEMM_BLKS + WO_T_BLKS, 256, GEMM_SMEM>>>(
        hsr, wqkvT, qkv, wo, woT, cs, sn, kh, vt);

    // #3: flash attention (2 CTAs/SM, shuffle-P, fused Q-rope, base-2 softmax)
    flash_mma<<<dim3(S_LEN / 64, NH), 128, FB_SMEM>>>(qkv, cs, sn, kh, vt, ao);

    // #4: output projection (tf32 at the dispatch ceiling)
    gemm_mma<<<dim3(HID / GBN, S_LEN / GBM), 256, GEMM_SMEM>>>(ao, woT, out, S_LEN, HID, NQ);
}